// round 2
// baseline (speedup 1.0000x reference)
#include <cuda_runtime.h>
#include <math.h>
#include <stdint.h>

// ---------------- problem constants ----------------
#define BB    256     // batch
#define NTOT  175     // N*K + Q
#define NWAY  20
#define KSHOT 5
#define QN    75
#define DD    512
#define LL    4
#define KNEI  5
#define TAUINV 10.0f  // 1/TAU
#define NKQ   (NWAY*KSHOT)   // 100
#define CHUNKS 5
#define ROWS_PER_CHUNK 35

// ---------------- device scratch (no allocations allowed) ----------------
__device__ float g_V   [(size_t)BB*NTOT*DD];
__device__ float g_V0  [(size_t)BB*NTOT*DD];
__device__ float g_msg [(size_t)BB*NTOT*DD];
__device__ float g_gemm[(size_t)BB*NTOT*DD];
__device__ float g_P    [(size_t)BB*NWAY*DD];
__device__ float g_P0   [(size_t)BB*NWAY*DD];
__device__ float g_Pmsg [(size_t)BB*NWAY*DD];
__device__ float g_Pgemm[(size_t)BB*NWAY*DD];
__device__ float g_Pa   [(size_t)BB*NWAY*DD];
__device__ float g_sim [(size_t)BB*NTOT*NTOT];
__device__ int   g_idx [(size_t)BB*NTOT*KNEI];
__device__ float g_w   [(size_t)BB*NTOT*KNEI];
__device__ float g_lossP[BB*CHUNKS];
__device__ int   g_accP [BB*CHUNKS];

// ---------------- helpers ----------------
__device__ __forceinline__ float blockSum(float v, float* red) {
    int tid = threadIdx.x;
    #pragma unroll
    for (int off = 16; off; off >>= 1) v += __shfl_down_sync(0xffffffffu, v, off);
    if ((tid & 31) == 0) red[tid >> 5] = v;
    __syncthreads();
    float r = 0.f;
    int nw = blockDim.x >> 5;
    if (tid < 32) {
        if (tid < nw) r = red[tid];
        #pragma unroll
        for (int off = 16; off; off >>= 1) r += __shfl_down_sync(0xffffffffu, r, off);
        if (tid == 0) red[0] = r;
    }
    __syncthreads();
    r = red[0];
    __syncthreads();
    return r;
}

__device__ __forceinline__ uint32_t f2tf32(float x) {
    uint32_t r;
    asm("cvt.rna.tf32.f32 %0, %1;" : "=r"(r) : "f"(x));
    return r;
}

__device__ __forceinline__ void mma8(float* c, const uint32_t* a, const uint32_t* b) {
    asm volatile(
        "mma.sync.aligned.m16n8k8.row.col.f32.tf32.tf32.f32 "
        "{%0,%1,%2,%3}, {%4,%5,%6,%7}, {%8,%9}, {%0,%1,%2,%3};"
        : "+f"(c[0]), "+f"(c[1]), "+f"(c[2]), "+f"(c[3])
        : "r"(a[0]), "r"(a[1]), "r"(a[2]), "r"(a[3]), "r"(b[0]), "r"(b[1]));
}

__device__ __forceinline__ float2 splitTF(float x) {
    uint32_t h = f2tf32(x);
    float hf = __uint_as_float(h);
    float lo = x - hf;
    return make_float2(hf, __uint_as_float(f2tf32(lo)));
}

// ---------------- kernels ----------------

__global__ void k_zero() {
    int i = blockIdx.x * 256 + threadIdx.x;
    if (i < BB * CHUNKS) { g_lossP[i] = 0.f; g_accP[i] = 0; }
}

// l2-normalize rows, write to two destinations (x and its residual anchor x0)
__global__ void k_init(const float* __restrict__ in, float* __restrict__ out,
                       float* __restrict__ out0) {
    __shared__ float red[8];
    size_t row = blockIdx.x;
    int t = threadIdx.x;                    // 128 threads, 512/4 float4
    float4 v = ((const float4*)(in + row * DD))[t];
    float ss = v.x*v.x + v.y*v.y + v.z*v.z + v.w*v.w;
    ss = blockSum(ss, red);
    float inv = 1.f / fmaxf(sqrtf(ss), 1e-12f);
    float4 o = make_float4(v.x*inv, v.y*inv, v.z*inv, v.w*inv);
    ((float4*)(out  + row * DD))[t] = o;
    ((float4*)(out0 + row * DD))[t] = o;
}

// ======================= tensor-core NT GEMM =======================
// C[m,n] = sum_k A[m,k]*B[n,k]  (row-major A [M,K], row-major B [N,K])
// 3xTF32 split for ~fp32 accuracy. Block tile 128x128, BK=8, double-buffered,
// smem holds interleaved (hi,lo) float2 per element.
__global__ __launch_bounds__(512) void k_mma_nt(
    const float* __restrict__ A, const float* __restrict__ Bm, float* __restrict__ C,
    int M, int N, int K, size_t strA, size_t strB, size_t strC)
{
    __shared__ float2 sA[2][128 * 9];
    __shared__ float2 sB[2][128 * 9];

    const float* Ab = A  + (size_t)blockIdx.z * strA;
    const float* Bb = Bm + (size_t)blockIdx.z * strB;
    float*       Cb = C  + (size_t)blockIdx.z * strC;

    int tid = threadIdx.x;
    int m0 = blockIdx.y * 128, n0 = blockIdx.x * 128;
    int warp = tid >> 5, lane = tid & 31;
    int warpM = warp >> 2, warpN = warp & 3;

    // staging: thread -> (row, colpair)
    int lrow = tid >> 2;
    int lcol = (tid & 3) * 2;
    int arow = m0 + lrow, brow = n0 + lrow;
    bool aok = arow < M, bok = brow < N;
    const float* Aptr = Ab + (size_t)arow * K + lcol;
    const float* Bptr = Bb + (size_t)brow * K + lcol;

    float acc[2][4][4];
    #pragma unroll
    for (int mt = 0; mt < 2; mt++)
        #pragma unroll
        for (int nt = 0; nt < 4; nt++)
            #pragma unroll
            for (int r = 0; r < 4; r++) acc[mt][nt][r] = 0.f;

    const int niter = K >> 3;   // BK = 8

    // prefetch iter 0
    float2 aIn = aok ? *(const float2*)(Aptr) : make_float2(0.f, 0.f);
    float2 bIn = bok ? *(const float2*)(Bptr) : make_float2(0.f, 0.f);
    sA[0][lrow * 9 + lcol]     = splitTF(aIn.x);
    sA[0][lrow * 9 + lcol + 1] = splitTF(aIn.y);
    sB[0][lrow * 9 + lcol]     = splitTF(bIn.x);
    sB[0][lrow * 9 + lcol + 1] = splitTF(bIn.y);
    __syncthreads();

    int buf = 0;
    int fr = lane >> 2, fc = lane & 3;
    for (int it = 0; it < niter; it++) {
        float2 aNx, bNx;
        bool more = (it + 1) < niter;
        if (more) {
            int k0 = (it + 1) << 3;
            aNx = aok ? *(const float2*)(Aptr + k0) : make_float2(0.f, 0.f);
            bNx = bok ? *(const float2*)(Bptr + k0) : make_float2(0.f, 0.f);
        }
        // fragments
        uint32_t ah[2][4], al[2][4];
        #pragma unroll
        for (int mt = 0; mt < 2; mt++) {
            int row0 = warpM * 32 + mt * 16 + fr;
            float2 v0 = sA[buf][row0 * 9 + fc];
            float2 v1 = sA[buf][(row0 + 8) * 9 + fc];
            float2 v2 = sA[buf][row0 * 9 + fc + 4];
            float2 v3 = sA[buf][(row0 + 8) * 9 + fc + 4];
            ah[mt][0] = __float_as_uint(v0.x); al[mt][0] = __float_as_uint(v0.y);
            ah[mt][1] = __float_as_uint(v1.x); al[mt][1] = __float_as_uint(v1.y);
            ah[mt][2] = __float_as_uint(v2.x); al[mt][2] = __float_as_uint(v2.y);
            ah[mt][3] = __float_as_uint(v3.x); al[mt][3] = __float_as_uint(v3.y);
        }
        uint32_t bh[4][2], bl[4][2];
        #pragma unroll
        for (int nt = 0; nt < 4; nt++) {
            int nrow = warpN * 32 + nt * 8 + fr;
            float2 w0 = sB[buf][nrow * 9 + fc];
            float2 w1 = sB[buf][nrow * 9 + fc + 4];
            bh[nt][0] = __float_as_uint(w0.x); bl[nt][0] = __float_as_uint(w0.y);
            bh[nt][1] = __float_as_uint(w1.x); bl[nt][1] = __float_as_uint(w1.y);
        }
        #pragma unroll
        for (int mt = 0; mt < 2; mt++)
            #pragma unroll
            for (int nt = 0; nt < 4; nt++) {
                mma8(acc[mt][nt], ah[mt], bh[nt]);
                mma8(acc[mt][nt], ah[mt], bl[nt]);
                mma8(acc[mt][nt], al[mt], bh[nt]);
            }
        if (more) {
            int nb = buf ^ 1;
            sA[nb][lrow * 9 + lcol]     = splitTF(aNx.x);
            sA[nb][lrow * 9 + lcol + 1] = splitTF(aNx.y);
            sB[nb][lrow * 9 + lcol]     = splitTF(bNx.x);
            sB[nb][lrow * 9 + lcol + 1] = splitTF(bNx.y);
        }
        __syncthreads();
        buf ^= 1;
    }

    // epilogue
    #pragma unroll
    for (int mt = 0; mt < 2; mt++) {
        #pragma unroll
        for (int nt = 0; nt < 4; nt++) {
            int row = m0 + warpM * 32 + mt * 16 + fr;
            int col = n0 + warpN * 32 + nt * 8 + fc * 2;
            if (row < M) {
                if (col < N)     Cb[(size_t)row * N + col]     = acc[mt][nt][0];
                if (col + 1 < N) Cb[(size_t)row * N + col + 1] = acc[mt][nt][1];
            }
            if (row + 8 < M) {
                if (col < N)     Cb[(size_t)(row + 8) * N + col]     = acc[mt][nt][2];
                if (col + 1 < N) Cb[(size_t)(row + 8) * N + col + 1] = acc[mt][nt][3];
            }
        }
    }
}

// per-row top-KNEI + softmax(vals/tau); one warp per row (instance graph)
__global__ void k_topk(const float* __restrict__ sim, int nCols, int totalRows,
                       int* __restrict__ idxOut, float* __restrict__ wOut)
{
    int row = blockIdx.x * 4 + (threadIdx.x >> 5);
    if (row >= totalRows) return;
    int lane = threadIdx.x & 31;
    const float* sr = sim + (size_t)row * nCols;
    float v[6];
    #pragma unroll
    for (int j = 0; j < 6; j++) {
        int c = lane + j * 32;
        v[j] = (c < nCols) ? sr[c] : -INFINITY;
    }
    float cv[KNEI]; int ci[KNEI];
    #pragma unroll
    for (int p = 0; p < KNEI; p++) {
        float bv = -INFINITY; int bc = 0x7fffffff;
        #pragma unroll
        for (int j = 0; j < 6; j++) {
            if (v[j] > bv) { bv = v[j]; bc = lane + j * 32; }
        }
        #pragma unroll
        for (int off = 16; off; off >>= 1) {
            float ov = __shfl_down_sync(0xffffffffu, bv, off);
            int   oc = __shfl_down_sync(0xffffffffu, bc, off);
            if (ov > bv || (ov == bv && oc < bc)) { bv = ov; bc = oc; }
        }
        bv = __shfl_sync(0xffffffffu, bv, 0);
        bc = __shfl_sync(0xffffffffu, bc, 0);
        cv[p] = bv; ci[p] = bc;
        if ((bc & 31) == lane) v[bc >> 5] = -INFINITY;
    }
    if (lane == 0) {
        float mx = cv[0];
        float e[KNEI], s = 0.f;
        #pragma unroll
        for (int p = 0; p < KNEI; p++) { e[p] = expf((cv[p] - mx) * TAUINV); s += e[p]; }
        float inv = 1.f / s;
        #pragma unroll
        for (int p = 0; p < KNEI; p++) {
            idxOut[(size_t)row * KNEI + p] = ci[p];
            wOut [(size_t)row * KNEI + p] = e[p] * inv;
        }
    }
}

// msg[row,:] = sum_p w[p] * src[b, idx[p], :]   (sparse adj @ x)
__global__ void k_gather(const float* __restrict__ src, const int* __restrict__ idx,
                         const float* __restrict__ w, float* __restrict__ msg,
                         int rowsPerB)
{
    int row = blockIdx.x;
    int b = row / rowsPerB;
    const int*   ir = idx + (size_t)row * KNEI;
    const float* wr = w   + (size_t)row * KNEI;
    int   ji[KNEI]; float wj[KNEI];
    #pragma unroll
    for (int p = 0; p < KNEI; p++) { ji[p] = ir[p]; wj[p] = wr[p]; }
    const float* base = src + (size_t)b * rowsPerB * DD;
    int t = threadIdx.x;   // 128
    float4 acc = make_float4(0,0,0,0);
    #pragma unroll
    for (int p = 0; p < KNEI; p++) {
        float4 x = ((const float4*)(base + (size_t)ji[p] * DD))[t];
        acc.x += wj[p]*x.x; acc.y += wj[p]*x.y; acc.z += wj[p]*x.z; acc.w += wj[p]*x.w;
    }
    ((float4*)(msg + (size_t)row * DD))[t] = acc;
}

// fused prototype branch pre-GEMM: sims (20x20) + top-5 softmax + gather -> Pmsg
__global__ __launch_bounds__(256) void k_proto(const float* __restrict__ P,
                                               float* __restrict__ Pmsg)
{
    __shared__ float sP[NWAY * DD];        // 40KB
    __shared__ float sSim[NWAY][NWAY];
    __shared__ float sW[NWAY][KNEI];
    __shared__ int   sI[NWAY][KNEI];
    int b = blockIdx.x, tid = threadIdx.x;
    const float* Pb = P + (size_t)b * NWAY * DD;
    for (int i = tid; i < NWAY * DD; i += 256)
        sP[i] = Pb[i];
    __syncthreads();
    int warp = tid >> 5, lane = tid & 31;
    for (int p = warp; p < NWAY * NWAY; p += 8) {
        int r = p / NWAY, c = p % NWAY;
        float d = 0.f;
        for (int i = lane; i < DD; i += 32) d += sP[r * DD + i] * sP[c * DD + i];
        #pragma unroll
        for (int off = 16; off; off >>= 1) d += __shfl_down_sync(0xffffffffu, d, off);
        if (lane == 0) sSim[r][c] = d;
    }
    __syncthreads();
    if (tid < NWAY) {
        float v[NWAY];
        #pragma unroll
        for (int c = 0; c < NWAY; c++) v[c] = sSim[tid][c];
        float cv[KNEI]; int ci[KNEI];
        #pragma unroll
        for (int p = 0; p < KNEI; p++) {
            float bv = -INFINITY; int bc = 0;
            #pragma unroll
            for (int c = 0; c < NWAY; c++)
                if (v[c] > bv) { bv = v[c]; bc = c; }
            cv[p] = bv; ci[p] = bc; v[bc] = -INFINITY;
        }
        float mx = cv[0], e[KNEI], s = 0.f;
        #pragma unroll
        for (int p = 0; p < KNEI; p++) { e[p] = expf((cv[p] - mx) * TAUINV); s += e[p]; }
        float inv = 1.f / s;
        #pragma unroll
        for (int p = 0; p < KNEI; p++) { sW[tid][p] = e[p] * inv; sI[tid][p] = ci[p]; }
    }
    __syncthreads();
    float* Mb = Pmsg + (size_t)b * NWAY * DD;
    for (int e = tid; e < NWAY * DD; e += 256) {
        int r = e >> 9, d = e & (DD - 1);
        float a = 0.f;
        #pragma unroll
        for (int p = 0; p < KNEI; p++) a += sW[r][p] * sP[sI[r][p] * DD + d];
        Mb[e] = a;
    }
}

// x = l2n(0.8*(x + s*tanh(G + bias)) + 0.2*x0)
__global__ void k_epi(float* __restrict__ X, const float* __restrict__ X0,
                      const float* __restrict__ G, const float* __restrict__ bias,
                      const float* __restrict__ scaleArr, int layer)
{
    __shared__ float red[8];
    size_t row = blockIdx.x;
    float s = scaleArr[layer];
    int t = threadIdx.x;  // 128
    float4 vv = ((const float4*)(X  + row * DD))[t];
    float4 gg = ((const float4*)(G  + row * DD))[t];
    float4 bb = ((const float4*)(bias))[t];
    float4 v0 = ((const float4*)(X0 + row * DD))[t];
    float4 r4;
    r4.x = 0.8f*(vv.x + s*tanhf(gg.x + bb.x)) + 0.2f*v0.x;
    r4.y = 0.8f*(vv.y + s*tanhf(gg.y + bb.y)) + 0.2f*v0.y;
    r4.z = 0.8f*(vv.z + s*tanhf(gg.z + bb.z)) + 0.2f*v0.z;
    r4.w = 0.8f*(vv.w + s*tanhf(gg.w + bb.w)) + 0.2f*v0.w;
    float ss = r4.x*r4.x + r4.y*r4.y + r4.z*r4.z + r4.w*r4.w;
    ss = blockSum(ss, red);
    float inv = 1.f / fmaxf(sqrtf(ss), 1e-12f);
    r4.x*=inv; r4.y*=inv; r4.z*=inv; r4.w*=inv;
    ((float4*)(X + row * DD))[t] = r4;
}

// VC = l2n(mean_k V_support); Pa = l2n(alpha*P + (1-alpha)*VC)
__global__ void k_vc_pa(const float* __restrict__ V, const float* __restrict__ P,
                        float* __restrict__ Pa, const float* __restrict__ alphaPtr)
{
    __shared__ float red[8];
    int b = blockIdx.x, c = blockIdx.y;
    int t = threadIdx.x;  // 128
    const float* base = V + ((size_t)b * NTOT + (size_t)c * KSHOT) * DD;
    float4 s4 = make_float4(0,0,0,0);
    #pragma unroll
    for (int k = 0; k < KSHOT; k++) {
        float4 x = ((const float4*)(base + (size_t)k * DD))[t];
        s4.x += x.x; s4.y += x.y; s4.z += x.z; s4.w += x.w;
    }
    s4.x *= 0.2f; s4.y *= 0.2f; s4.z *= 0.2f; s4.w *= 0.2f;
    float ss = s4.x*s4.x + s4.y*s4.y + s4.z*s4.z + s4.w*s4.w;
    ss = blockSum(ss, red);
    float inv = 1.f / fmaxf(sqrtf(ss), 1e-12f);
    float a = *alphaPtr;
    float4 p4 = ((const float4*)(P + ((size_t)b * NWAY + c) * DD))[t];
    float4 pa;
    pa.x = a*p4.x + (1.f-a)*s4.x*inv;
    pa.y = a*p4.y + (1.f-a)*s4.y*inv;
    pa.z = a*p4.z + (1.f-a)*s4.z*inv;
    pa.w = a*p4.w + (1.f-a)*s4.w*inv;
    float ss2 = pa.x*pa.x + pa.y*pa.y + pa.z*pa.z + pa.w*pa.w;
    ss2 = blockSum(ss2, red);
    float inv2 = 1.f / fmaxf(sqrtf(ss2), 1e-12f);
    pa.x*=inv2; pa.y*=inv2; pa.z*=inv2; pa.w*=inv2;
    ((float4*)(Pa + ((size_t)b * NWAY + c) * DD))[t] = pa;
}

// cross-modal guidance + per-step logits/CE (+argmax acc on last layer)
__global__ __launch_bounds__(256) void k_guide(
    float* __restrict__ V, const float* __restrict__ Pa,
    const float* __restrict__ betaPtr, const int* __restrict__ qy, int layer)
{
    __shared__ float sPa[NWAY * DD];
    __shared__ float sV[DD];
    __shared__ float sims[NWAY];
    __shared__ float soft[NWAY];
    __shared__ float red[8];
    __shared__ float sInv;
    int b = blockIdx.x, chunk = blockIdx.y;
    int tid = threadIdx.x;
    float beta = *betaPtr;
    const float* PaB = Pa + (size_t)b * NWAY * DD;
    for (int i = tid; i < NWAY * DD; i += 256) sPa[i] = PaB[i];
    __syncthreads();
    int warp = tid >> 5, lane = tid & 31;
    float localLoss = 0.f; int localAcc = 0;
    for (int n = chunk * ROWS_PER_CHUNK; n < chunk * ROWS_PER_CHUNK + ROWS_PER_CHUNK; n++) {
        float* Vrow = V + ((size_t)b * NTOT + n) * DD;
        for (int i = tid; i < DD; i += 256) sV[i] = Vrow[i];
        __syncthreads();
        for (int m = warp; m < NWAY; m += 8) {
            float d = 0.f;
            for (int i = lane; i < DD; i += 32) d += sV[i] * sPa[m * DD + i];
            #pragma unroll
            for (int off = 16; off; off >>= 1) d += __shfl_down_sync(0xffffffffu, d, off);
            if (lane == 0) sims[m] = d;
        }
        __syncthreads();
        if (tid == 0) {
            float mx = -1e30f;
            for (int m = 0; m < NWAY; m++) mx = fmaxf(mx, sims[m]);
            float s = 0.f;
            for (int m = 0; m < NWAY; m++) { float e = expf((sims[m] - mx) * TAUINV); soft[m] = e; s += e; }
            float inv = 1.f / s;
            for (int m = 0; m < NWAY; m++) soft[m] *= inv;
        }
        __syncthreads();
        int d0 = tid, d1 = tid + 256;
        float g0 = 0.f, g1 = 0.f;
        #pragma unroll
        for (int m = 0; m < NWAY; m++) {
            g0 += soft[m] * sPa[m * DD + d0];
            g1 += soft[m] * sPa[m * DD + d1];
        }
        float nv0 = beta * sV[d0] + (1.f - beta) * g0;
        float nv1 = beta * sV[d1] + (1.f - beta) * g1;
        float ss = nv0 * nv0 + nv1 * nv1;
        ss = blockSum(ss, red);
        if (tid == 0) sInv = 1.f / fmaxf(sqrtf(ss), 1e-12f);
        __syncthreads();
        nv0 *= sInv; nv1 *= sInv;
        Vrow[d0] = nv0; Vrow[d1] = nv1;
        sV[d0] = nv0; sV[d1] = nv1;
        __syncthreads();
        if (n >= NKQ) {
            for (int m = warp; m < NWAY; m += 8) {
                float d = 0.f;
                for (int i = lane; i < DD; i += 32) d += sV[i] * sPa[m * DD + i];
                #pragma unroll
                for (int off = 16; off; off >>= 1) d += __shfl_down_sync(0xffffffffu, d, off);
                if (lane == 0) sims[m] = 5.0f * d;   // LOGIT_SCALE
            }
            __syncthreads();
            if (tid == 0) {
                float mx = -1e30f; int am = 0;
                for (int m = 0; m < NWAY; m++) if (sims[m] > mx) { mx = sims[m]; am = m; }
                float s = 0.f;
                for (int m = 0; m < NWAY; m++) s += expf(sims[m] - mx);
                float lse = mx + logf(s);
                int lbl = qy[b * QN + (n - NKQ)];
                localLoss += lse - sims[lbl];
                if (layer == LL - 1) localAcc += (am == lbl) ? 1 : 0;
            }
            __syncthreads();
        }
    }
    if (tid == 0) {
        int pi = b * CHUNKS + chunk;
        g_lossP[pi] += localLoss;
        if (layer == LL - 1) g_accP[pi] = localAcc;
    }
}

__global__ void k_final(float* __restrict__ out) {
    __shared__ float red[8];
    int t = threadIdx.x;  // 256
    float ls = 0.f; float ac = 0.f;
    for (int i = t; i < BB * CHUNKS; i += 256) { ls += g_lossP[i]; ac += (float)g_accP[i]; }
    float L = blockSum(ls, red);
    float A = blockSum(ac, red);
    if (t == 0) {
        out[0] = L / (float)(BB * QN * LL);
        out[1] = A / (float)(BB * QN);
    }
}

// ---------------- launch ----------------
extern "C" void kernel_launch(void* const* d_in, const int* in_sizes, int n_in,
                              void* d_out, int out_size)
{
    const float* V_feat = (const float*)d_in[0];
    const float* P_feat = (const float*)d_in[1];
    const int*   qy     = (const int*)  d_in[2];
    const float* igbW   = (const float*)d_in[3];
    const float* igbB   = (const float*)d_in[4];
    const float* igbS   = (const float*)d_in[5];
    const float* pgbW   = (const float*)d_in[6];
    const float* pgbB   = (const float*)d_in[7];
    const float* pgbS   = (const float*)d_in[8];
    const float* alpha  = (const float*)d_in[9];
    const float* beta   = (const float*)d_in[10];
    float* out = (float*)d_out;

    float *pV, *pV0, *pMsg, *pGemm, *pP, *pP0, *pPmsg, *pPgemm, *pPa, *pSim, *pW;
    int *pIdx;
    cudaGetSymbolAddress((void**)&pV,    g_V);
    cudaGetSymbolAddress((void**)&pV0,   g_V0);
    cudaGetSymbolAddress((void**)&pMsg,  g_msg);
    cudaGetSymbolAddress((void**)&pGemm, g_gemm);
    cudaGetSymbolAddress((void**)&pP,    g_P);
    cudaGetSymbolAddress((void**)&pP0,   g_P0);
    cudaGetSymbolAddress((void**)&pPmsg, g_Pmsg);
    cudaGetSymbolAddress((void**)&pPgemm,g_Pgemm);
    cudaGetSymbolAddress((void**)&pPa,   g_Pa);
    cudaGetSymbolAddress((void**)&pSim,  g_sim);
    cudaGetSymbolAddress((void**)&pW,    g_w);
    cudaGetSymbolAddress((void**)&pIdx,  g_idx);

    k_zero<<<(BB * CHUNKS + 255) / 256, 256>>>();
    k_init<<<BB * NTOT, 128>>>(V_feat, pV, pV0);
    k_init<<<BB * NWAY, 128>>>(P_feat, pP, pP0);

    for (int i = 0; i < LL; i++) {
        // ---- instance branch ----
        {
            dim3 gs((NTOT + 127) / 128, (NTOT + 127) / 128, BB);
            k_mma_nt<<<gs, 512>>>(pV, pV, pSim, NTOT, NTOT, DD,
                                  (size_t)NTOT * DD, (size_t)NTOT * DD, (size_t)NTOT * NTOT);
        }
        k_topk<<<(BB * NTOT + 3) / 4, 128>>>(pSim, NTOT, BB * NTOT, pIdx, pW);
        k_gather<<<BB * NTOT, 128>>>(pV, pIdx, pW, pMsg, NTOT);
        {
            dim3 gs(DD / 128, (BB * NTOT) / 128, 1);
            k_mma_nt<<<gs, 512>>>(pMsg, igbW + (size_t)i * DD * DD, pGemm,
                                  BB * NTOT, DD, DD, 0, 0, 0);
        }
        k_epi<<<BB * NTOT, 128>>>(pV, pV0, pGemm, igbB + (size_t)i * DD, igbS, i);
        // ---- prototype branch (fused sim/topk/gather) ----
        k_proto<<<BB, 256>>>(pP, pPmsg);
        {
            dim3 gs(DD / 128, (BB * NWAY) / 128, 1);
            k_mma_nt<<<gs, 512>>>(pPmsg, pgbW + (size_t)i * DD * DD, pPgemm,
                                  BB * NWAY, DD, DD, 0, 0, 0);
        }
        k_epi<<<BB * NWAY, 128>>>(pP, pP0, pPgemm, pgbB + (size_t)i * DD, pgbS, i);
        // ---- centers, adapted prototypes, guidance + logits/CE ----
        k_vc_pa<<<dim3(BB, NWAY), 128>>>(pV, pP, pPa, alpha);
        k_guide<<<dim3(BB, CHUNKS), 256>>>(pV, pPa, beta, qy, i);
    }
    k_final<<<1, 256>>>(out);
}

// round 3
// speedup vs baseline: 1.7853x; 1.7853x over previous
#include <cuda_runtime.h>
#include <cuda_bf16.h>
#include <math.h>
#include <stdint.h>

// ---------------- problem constants ----------------
#define BB    256     // batch
#define NTOT  175     // N*K + Q
#define NWAY  20
#define KSHOT 5
#define QN    75
#define DD    512
#define LL    4
#define KNEI  5
#define TAUINV 10.0f  // 1/TAU
#define NKQ   (NWAY*KSHOT)   // 100
#define CHUNKS 5
#define ROWS_PER_CHUNK 35

// ---------------- device scratch (no allocations allowed) ----------------
__device__ float g_V   [(size_t)BB*NTOT*DD];
__device__ float g_V0  [(size_t)BB*NTOT*DD];
__device__ float g_msg [(size_t)BB*NTOT*DD];
__device__ float g_gemm[(size_t)BB*NTOT*DD];
__device__ float g_P    [(size_t)BB*NWAY*DD];
__device__ float g_P0   [(size_t)BB*NWAY*DD];
__device__ float g_Pmsg [(size_t)BB*NWAY*DD];
__device__ float g_Pgemm[(size_t)BB*NWAY*DD];
__device__ float g_Pa   [(size_t)BB*NWAY*DD];
__device__ float g_sim [(size_t)BB*NTOT*NTOT];
__device__ int   g_idx [(size_t)BB*NTOT*KNEI];
__device__ float g_w   [(size_t)BB*NTOT*KNEI];
__device__ float g_lossP[BB*CHUNKS];
__device__ int   g_accP [BB*CHUNKS];

// ---------------- helpers ----------------
__device__ __forceinline__ float blockSum(float v, float* red) {
    int tid = threadIdx.x;
    #pragma unroll
    for (int off = 16; off; off >>= 1) v += __shfl_down_sync(0xffffffffu, v, off);
    if ((tid & 31) == 0) red[tid >> 5] = v;
    __syncthreads();
    float r = 0.f;
    int nw = blockDim.x >> 5;
    if (tid < 32) {
        if (tid < nw) r = red[tid];
        #pragma unroll
        for (int off = 16; off; off >>= 1) r += __shfl_down_sync(0xffffffffu, r, off);
        if (tid == 0) red[0] = r;
    }
    __syncthreads();
    r = red[0];
    __syncthreads();
    return r;
}

__device__ __forceinline__ uint32_t smem_u32(const void* p) {
    return (uint32_t)__cvta_generic_to_shared(p);
}

__device__ __forceinline__ void ldsm4(uint32_t& r0, uint32_t& r1, uint32_t& r2, uint32_t& r3,
                                      uint32_t addr) {
    asm volatile("ldmatrix.sync.aligned.m8n8.x4.shared.b16 {%0,%1,%2,%3}, [%4];"
                 : "=r"(r0), "=r"(r1), "=r"(r2), "=r"(r3) : "r"(addr));
}

__device__ __forceinline__ void mma16(float* c, const uint32_t* a, const uint32_t* b) {
    asm volatile(
        "mma.sync.aligned.m16n8k16.row.col.f32.bf16.bf16.f32 "
        "{%0,%1,%2,%3}, {%4,%5,%6,%7}, {%8,%9}, {%0,%1,%2,%3};"
        : "+f"(c[0]), "+f"(c[1]), "+f"(c[2]), "+f"(c[3])
        : "r"(a[0]), "r"(a[1]), "r"(a[2]), "r"(a[3]), "r"(b[0]), "r"(b[1]));
}

// split 8 consecutive f32 into hi/lo bf16 packed as uint4 each
__device__ __forceinline__ void split8(const float* x, uint4& hv, uint4& lv) {
    uint32_t h[4], l[4];
    #pragma unroll
    for (int i = 0; i < 4; i++) {
        __nv_bfloat16 h0 = __float2bfloat16(x[2*i]);
        __nv_bfloat16 h1 = __float2bfloat16(x[2*i+1]);
        __nv_bfloat16 l0 = __float2bfloat16(x[2*i]   - __bfloat162float(h0));
        __nv_bfloat16 l1 = __float2bfloat16(x[2*i+1] - __bfloat162float(h1));
        h[i] = (uint32_t)__bfloat16_as_ushort(h0) | ((uint32_t)__bfloat16_as_ushort(h1) << 16);
        l[i] = (uint32_t)__bfloat16_as_ushort(l0) | ((uint32_t)__bfloat16_as_ushort(l1) << 16);
    }
    hv = make_uint4(h[0], h[1], h[2], h[3]);
    lv = make_uint4(l[0], l[1], l[2], l[3]);
}

// ---------------- kernels ----------------

__global__ void k_zero() {
    int i = blockIdx.x * 256 + threadIdx.x;
    if (i < BB * CHUNKS) { g_lossP[i] = 0.f; g_accP[i] = 0; }
}

__global__ void k_init(const float* __restrict__ in, float* __restrict__ out,
                       float* __restrict__ out0) {
    __shared__ float red[8];
    size_t row = blockIdx.x;
    int t = threadIdx.x;                    // 128 threads
    float4 v = ((const float4*)(in + row * DD))[t];
    float ss = v.x*v.x + v.y*v.y + v.z*v.z + v.w*v.w;
    ss = blockSum(ss, red);
    float inv = 1.f / fmaxf(sqrtf(ss), 1e-12f);
    float4 o = make_float4(v.x*inv, v.y*inv, v.z*inv, v.w*inv);
    ((float4*)(out  + row * DD))[t] = o;
    ((float4*)(out0 + row * DD))[t] = o;
}

// ============== bf16-split tensor-core NT GEMM ==============
// C[m,n] = sum_k A[m,k]*B[n,k]; A[M,K], B[N,K] row-major.
// Split x = hi + lo (bf16); C = Ah*Bh + Ah*Bl + Al*Bh (fp32 accum).
// smem: hi/lo arrays, xor-swizzled 8-elem (16B) chunks, ldmatrix loads.
template<int BM, int BN, int WARPS_M, int WARPS_N>
__global__ __launch_bounds__(WARPS_M*WARPS_N*32) void k_gemm_bf(
    const float* __restrict__ A, const float* __restrict__ Bm, float* __restrict__ C,
    int M, int N, int K, size_t strA, size_t strB, size_t strC)
{
    constexpr int NT = WARPS_M * WARPS_N * 32;
    constexpr int WM = BM / WARPS_M;
    constexpr int WN = BN / WARPS_N;
    constexpr int TM = WM / 16;
    constexpr int TN = WN / 8;
    constexpr int BK = 32;
    constexpr int CH_A = BM * (BK/8);   // 16B chunks in A stage
    constexpr int PT_A = CH_A / NT;     // chunks per thread (=2)
    constexpr int CH_B = BN * (BK/8);
    constexpr int PT_B = CH_B / NT;

    __shared__ __nv_bfloat16 sAh[BM*BK], sAl[BM*BK], sBh[BN*BK], sBl[BN*BK];

    const float* Ab = A  + (size_t)blockIdx.z * strA;
    const float* Bb = Bm + (size_t)blockIdx.z * strB;
    float*       Cb = C  + (size_t)blockIdx.z * strC;

    int tid = threadIdx.x;
    int m0 = blockIdx.y * BM, n0 = blockIdx.x * BN;
    int warp = tid >> 5, lane = tid & 31;
    int warpM = warp / WARPS_N, warpN = warp % WARPS_N;
    int wmo = warpM * WM, wno = warpN * WN;

    // staging coords (chunk = (row, kc)); smem elem offset = row*BK + ((kc^(row&3))<<3)
    int sRowA[PT_A], sKcA[PT_A]; bool okA[PT_A]; const float* gA[PT_A];
    #pragma unroll
    for (int i = 0; i < PT_A; i++) {
        int c = tid + i * NT;
        sRowA[i] = c >> 2; sKcA[i] = c & 3;
        int gr = m0 + sRowA[i];
        okA[i] = gr < M;
        gA[i] = Ab + (size_t)(okA[i] ? gr : 0) * K + sKcA[i] * 8;
    }
    int sRowB[PT_B], sKcB[PT_B]; bool okB[PT_B]; const float* gB[PT_B];
    #pragma unroll
    for (int i = 0; i < PT_B; i++) {
        int c = tid + i * NT;
        sRowB[i] = c >> 2; sKcB[i] = c & 3;
        int gr = n0 + sRowB[i];
        okB[i] = gr < N;
        gB[i] = Bb + (size_t)(okB[i] ? gr : 0) * K + sKcB[i] * 8;
    }

    // fragment ldmatrix byte offsets (loop invariant; k16-step toggles ^32)
    uint32_t offA[TM], offB2[TN/2];
    {
        int j = lane >> 3, r8 = lane & 7;
        #pragma unroll
        for (int mt = 0; mt < TM; mt++) {
            int row = wmo + mt*16 + (j & 1) * 8 + r8;
            int kc = (j >> 1);
            offA[mt] = (uint32_t)((row * BK + ((kc ^ (row & 3)) << 3)) * 2);
        }
        #pragma unroll
        for (int nt2 = 0; nt2 < TN/2; nt2++) {
            int n = wno + nt2*16 + (j >> 1) * 8 + r8;
            int kc = (j & 1);
            offB2[nt2] = (uint32_t)((n * BK + ((kc ^ (n & 3)) << 3)) * 2);
        }
    }
    uint32_t baseAh = smem_u32(sAh), baseAl = smem_u32(sAl);
    uint32_t baseBh = smem_u32(sBh), baseBl = smem_u32(sBl);

    float acc[TM][TN][4];
    #pragma unroll
    for (int mt = 0; mt < TM; mt++)
        #pragma unroll
        for (int nt = 0; nt < TN; nt++)
            #pragma unroll
            for (int r = 0; r < 4; r++) acc[mt][nt][r] = 0.f;

    const int iters = K / BK;
    float regA[PT_A][8], regB[PT_B][8];

    // prologue: load + stage iter 0
    #pragma unroll
    for (int i = 0; i < PT_A; i++) {
        float4 x0 = okA[i] ? *(const float4*)(gA[i])     : make_float4(0,0,0,0);
        float4 x1 = okA[i] ? *(const float4*)(gA[i] + 4) : make_float4(0,0,0,0);
        regA[i][0]=x0.x; regA[i][1]=x0.y; regA[i][2]=x0.z; regA[i][3]=x0.w;
        regA[i][4]=x1.x; regA[i][5]=x1.y; regA[i][6]=x1.z; regA[i][7]=x1.w;
    }
    #pragma unroll
    for (int i = 0; i < PT_B; i++) {
        float4 x0 = okB[i] ? *(const float4*)(gB[i])     : make_float4(0,0,0,0);
        float4 x1 = okB[i] ? *(const float4*)(gB[i] + 4) : make_float4(0,0,0,0);
        regB[i][0]=x0.x; regB[i][1]=x0.y; regB[i][2]=x0.z; regB[i][3]=x0.w;
        regB[i][4]=x1.x; regB[i][5]=x1.y; regB[i][6]=x1.z; regB[i][7]=x1.w;
    }
    #pragma unroll
    for (int i = 0; i < PT_A; i++) {
        int off = sRowA[i] * BK + ((sKcA[i] ^ (sRowA[i] & 3)) << 3);
        uint4 hv, lv; split8(regA[i], hv, lv);
        *(uint4*)(sAh + off) = hv; *(uint4*)(sAl + off) = lv;
    }
    #pragma unroll
    for (int i = 0; i < PT_B; i++) {
        int off = sRowB[i] * BK + ((sKcB[i] ^ (sRowB[i] & 3)) << 3);
        uint4 hv, lv; split8(regB[i], hv, lv);
        *(uint4*)(sBh + off) = hv; *(uint4*)(sBl + off) = lv;
    }
    __syncthreads();

    for (int it = 0; ; ) {
        bool more = (it + 1) < iters;
        if (more) {
            int kg = (it + 1) * BK;
            #pragma unroll
            for (int i = 0; i < PT_A; i++) {
                float4 x0 = okA[i] ? *(const float4*)(gA[i] + kg)     : make_float4(0,0,0,0);
                float4 x1 = okA[i] ? *(const float4*)(gA[i] + kg + 4) : make_float4(0,0,0,0);
                regA[i][0]=x0.x; regA[i][1]=x0.y; regA[i][2]=x0.z; regA[i][3]=x0.w;
                regA[i][4]=x1.x; regA[i][5]=x1.y; regA[i][6]=x1.z; regA[i][7]=x1.w;
            }
            #pragma unroll
            for (int i = 0; i < PT_B; i++) {
                float4 x0 = okB[i] ? *(const float4*)(gB[i] + kg)     : make_float4(0,0,0,0);
                float4 x1 = okB[i] ? *(const float4*)(gB[i] + kg + 4) : make_float4(0,0,0,0);
                regB[i][0]=x0.x; regB[i][1]=x0.y; regB[i][2]=x0.z; regB[i][3]=x0.w;
                regB[i][4]=x1.x; regB[i][5]=x1.y; regB[i][6]=x1.z; regB[i][7]=x1.w;
            }
        }
        // compute both k16 steps from smem
        #pragma unroll
        for (int s = 0; s < 2; s++) {
            uint32_t sx = s * 32;   // toggle chunk bit1 = 32 bytes
            uint32_t ah[TM][4], al[TM][4], bh[TN][2], bl[TN][2];
            #pragma unroll
            for (int mt = 0; mt < TM; mt++) {
                ldsm4(ah[mt][0], ah[mt][1], ah[mt][2], ah[mt][3], baseAh + (offA[mt] ^ sx));
                ldsm4(al[mt][0], al[mt][1], al[mt][2], al[mt][3], baseAl + (offA[mt] ^ sx));
            }
            #pragma unroll
            for (int nt2 = 0; nt2 < TN/2; nt2++) {
                uint32_t r0,r1,r2,r3;
                ldsm4(r0, r1, r2, r3, baseBh + (offB2[nt2] ^ sx));
                bh[nt2*2][0]=r0; bh[nt2*2][1]=r1; bh[nt2*2+1][0]=r2; bh[nt2*2+1][1]=r3;
                ldsm4(r0, r1, r2, r3, baseBl + (offB2[nt2] ^ sx));
                bl[nt2*2][0]=r0; bl[nt2*2][1]=r1; bl[nt2*2+1][0]=r2; bl[nt2*2+1][1]=r3;
            }
            #pragma unroll
            for (int mt = 0; mt < TM; mt++)
                #pragma unroll
                for (int nt = 0; nt < TN; nt++) {
                    mma16(acc[mt][nt], ah[mt], bh[nt]);
                    mma16(acc[mt][nt], ah[mt], bl[nt]);
                    mma16(acc[mt][nt], al[mt], bh[nt]);
                }
        }
        if (!more) break;
        __syncthreads();
        #pragma unroll
        for (int i = 0; i < PT_A; i++) {
            int off = sRowA[i] * BK + ((sKcA[i] ^ (sRowA[i] & 3)) << 3);
            uint4 hv, lv; split8(regA[i], hv, lv);
            *(uint4*)(sAh + off) = hv; *(uint4*)(sAl + off) = lv;
        }
        #pragma unroll
        for (int i = 0; i < PT_B; i++) {
            int off = sRowB[i] * BK + ((sKcB[i] ^ (sRowB[i] & 3)) << 3);
            uint4 hv, lv; split8(regB[i], hv, lv);
            *(uint4*)(sBh + off) = hv; *(uint4*)(sBl + off) = lv;
        }
        __syncthreads();
        it++;
    }

    // epilogue
    #pragma unroll
    for (int mt = 0; mt < TM; mt++) {
        #pragma unroll
        for (int nt = 0; nt < TN; nt++) {
            int row = m0 + wmo + mt*16 + (lane >> 2);
            int col = n0 + wno + nt*8 + (lane & 3) * 2;
            if (row < M && col < N) {
                Cb[(size_t)row * N + col]     = acc[mt][nt][0];
                if (col + 1 < N) Cb[(size_t)row * N + col + 1] = acc[mt][nt][1];
            }
            if (row + 8 < M && col < N) {
                Cb[(size_t)(row + 8) * N + col]     = acc[mt][nt][2];
                if (col + 1 < N) Cb[(size_t)(row + 8) * N + col + 1] = acc[mt][nt][3];
            }
        }
    }
}

// per-row top-KNEI + softmax(vals/tau); one warp per row (instance graph)
__global__ void k_topk(const float* __restrict__ sim, int nCols, int totalRows,
                       int* __restrict__ idxOut, float* __restrict__ wOut)
{
    int row = blockIdx.x * 4 + (threadIdx.x >> 5);
    if (row >= totalRows) return;
    int lane = threadIdx.x & 31;
    const float* sr = sim + (size_t)row * nCols;
    float v[6];
    #pragma unroll
    for (int j = 0; j < 6; j++) {
        int c = lane + j * 32;
        v[j] = (c < nCols) ? sr[c] : -INFINITY;
    }
    float cv[KNEI]; int ci[KNEI];
    #pragma unroll
    for (int p = 0; p < KNEI; p++) {
        float bv = -INFINITY; int bc = 0x7fffffff;
        #pragma unroll
        for (int j = 0; j < 6; j++) {
            if (v[j] > bv) { bv = v[j]; bc = lane + j * 32; }
        }
        #pragma unroll
        for (int off = 16; off; off >>= 1) {
            float ov = __shfl_down_sync(0xffffffffu, bv, off);
            int   oc = __shfl_down_sync(0xffffffffu, bc, off);
            if (ov > bv || (ov == bv && oc < bc)) { bv = ov; bc = oc; }
        }
        bv = __shfl_sync(0xffffffffu, bv, 0);
        bc = __shfl_sync(0xffffffffu, bc, 0);
        cv[p] = bv; ci[p] = bc;
        if ((bc & 31) == lane) v[bc >> 5] = -INFINITY;
    }
    if (lane == 0) {
        float mx = cv[0];
        float e[KNEI], s = 0.f;
        #pragma unroll
        for (int p = 0; p < KNEI; p++) { e[p] = expf((cv[p] - mx) * TAUINV); s += e[p]; }
        float inv = 1.f / s;
        #pragma unroll
        for (int p = 0; p < KNEI; p++) {
            idxOut[(size_t)row * KNEI + p] = ci[p];
            wOut [(size_t)row * KNEI + p] = e[p] * inv;
        }
    }
}

// msg[row,:] = sum_p w[p] * src[b, idx[p], :]
__global__ void k_gather(const float* __restrict__ src, const int* __restrict__ idx,
                         const float* __restrict__ w, float* __restrict__ msg,
                         int rowsPerB)
{
    int row = blockIdx.x;
    int b = row / rowsPerB;
    const int*   ir = idx + (size_t)row * KNEI;
    const float* wr = w   + (size_t)row * KNEI;
    int   ji[KNEI]; float wj[KNEI];
    #pragma unroll
    for (int p = 0; p < KNEI; p++) { ji[p] = ir[p]; wj[p] = wr[p]; }
    const float* base = src + (size_t)b * rowsPerB * DD;
    int t = threadIdx.x;   // 128
    float4 acc = make_float4(0,0,0,0);
    #pragma unroll
    for (int p = 0; p < KNEI; p++) {
        float4 x = ((const float4*)(base + (size_t)ji[p] * DD))[t];
        acc.x += wj[p]*x.x; acc.y += wj[p]*x.y; acc.z += wj[p]*x.z; acc.w += wj[p]*x.w;
    }
    ((float4*)(msg + (size_t)row * DD))[t] = acc;
}

// fused prototype branch pre-GEMM: sims (20x20) + top-5 softmax + gather -> Pmsg
__global__ __launch_bounds__(256) void k_proto(const float* __restrict__ P,
                                               float* __restrict__ Pmsg)
{
    __shared__ float sP[NWAY * DD];
    __shared__ float sSim[NWAY][NWAY];
    __shared__ float sW[NWAY][KNEI];
    __shared__ int   sI[NWAY][KNEI];
    int b = blockIdx.x, tid = threadIdx.x;
    const float* Pb = P + (size_t)b * NWAY * DD;
    for (int i = tid; i < NWAY * DD; i += 256) sP[i] = Pb[i];
    __syncthreads();
    int warp = tid >> 5, lane = tid & 31;
    for (int p = warp; p < NWAY * NWAY; p += 8) {
        int r = p / NWAY, c = p % NWAY;
        float d = 0.f;
        for (int i = lane; i < DD; i += 32) d += sP[r * DD + i] * sP[c * DD + i];
        #pragma unroll
        for (int off = 16; off; off >>= 1) d += __shfl_down_sync(0xffffffffu, d, off);
        if (lane == 0) sSim[r][c] = d;
    }
    __syncthreads();
    if (tid < NWAY) {
        float v[NWAY];
        #pragma unroll
        for (int c = 0; c < NWAY; c++) v[c] = sSim[tid][c];
        float cv[KNEI]; int ci[KNEI];
        #pragma unroll
        for (int p = 0; p < KNEI; p++) {
            float bv = -INFINITY; int bc = 0;
            #pragma unroll
            for (int c = 0; c < NWAY; c++)
                if (v[c] > bv) { bv = v[c]; bc = c; }
            cv[p] = bv; ci[p] = bc; v[bc] = -INFINITY;
        }
        float mx = cv[0], e[KNEI], s = 0.f;
        #pragma unroll
        for (int p = 0; p < KNEI; p++) { e[p] = expf((cv[p] - mx) * TAUINV); s += e[p]; }
        float inv = 1.f / s;
        #pragma unroll
        for (int p = 0; p < KNEI; p++) { sW[tid][p] = e[p] * inv; sI[tid][p] = ci[p]; }
    }
    __syncthreads();
    float* Mb = Pmsg + (size_t)b * NWAY * DD;
    for (int e = tid; e < NWAY * DD; e += 256) {
        int r = e >> 9, d = e & (DD - 1);
        float a = 0.f;
        #pragma unroll
        for (int p = 0; p < KNEI; p++) a += sW[r][p] * sP[sI[r][p] * DD + d];
        Mb[e] = a;
    }
}

// x = l2n(0.8*(x + s*tanh(G + bias)) + 0.2*x0)
__global__ void k_epi(float* __restrict__ X, const float* __restrict__ X0,
                      const float* __restrict__ G, const float* __restrict__ bias,
                      const float* __restrict__ scaleArr, int layer)
{
    __shared__ float red[8];
    size_t row = blockIdx.x;
    float s = scaleArr[layer];
    int t = threadIdx.x;  // 128
    float4 vv = ((const float4*)(X  + row * DD))[t];
    float4 gg = ((const float4*)(G  + row * DD))[t];
    float4 bb = ((const float4*)(bias))[t];
    float4 v0 = ((const float4*)(X0 + row * DD))[t];
    float4 r4;
    r4.x = 0.8f*(vv.x + s*tanhf(gg.x + bb.x)) + 0.2f*v0.x;
    r4.y = 0.8f*(vv.y + s*tanhf(gg.y + bb.y)) + 0.2f*v0.y;
    r4.z = 0.8f*(vv.z + s*tanhf(gg.z + bb.z)) + 0.2f*v0.z;
    r4.w = 0.8f*(vv.w + s*tanhf(gg.w + bb.w)) + 0.2f*v0.w;
    float ss = r4.x*r4.x + r4.y*r4.y + r4.z*r4.z + r4.w*r4.w;
    ss = blockSum(ss, red);
    float inv = 1.f / fmaxf(sqrtf(ss), 1e-12f);
    r4.x*=inv; r4.y*=inv; r4.z*=inv; r4.w*=inv;
    ((float4*)(X + row * DD))[t] = r4;
}

// VC = l2n(mean_k V_support); Pa = l2n(alpha*P + (1-alpha)*VC)
__global__ void k_vc_pa(const float* __restrict__ V, const float* __restrict__ P,
                        float* __restrict__ Pa, const float* __restrict__ alphaPtr)
{
    __shared__ float red[8];
    int b = blockIdx.x, c = blockIdx.y;
    int t = threadIdx.x;  // 128
    const float* base = V + ((size_t)b * NTOT + (size_t)c * KSHOT) * DD;
    float4 s4 = make_float4(0,0,0,0);
    #pragma unroll
    for (int k = 0; k < KSHOT; k++) {
        float4 x = ((const float4*)(base + (size_t)k * DD))[t];
        s4.x += x.x; s4.y += x.y; s4.z += x.z; s4.w += x.w;
    }
    s4.x *= 0.2f; s4.y *= 0.2f; s4.z *= 0.2f; s4.w *= 0.2f;
    float ss = s4.x*s4.x + s4.y*s4.y + s4.z*s4.z + s4.w*s4.w;
    ss = blockSum(ss, red);
    float inv = 1.f / fmaxf(sqrtf(ss), 1e-12f);
    float a = *alphaPtr;
    float4 p4 = ((const float4*)(P + ((size_t)b * NWAY + c) * DD))[t];
    float4 pa;
    pa.x = a*p4.x + (1.f-a)*s4.x*inv;
    pa.y = a*p4.y + (1.f-a)*s4.y*inv;
    pa.z = a*p4.z + (1.f-a)*s4.z*inv;
    pa.w = a*p4.w + (1.f-a)*s4.w*inv;
    float ss2 = pa.x*pa.x + pa.y*pa.y + pa.z*pa.z + pa.w*pa.w;
    ss2 = blockSum(ss2, red);
    float inv2 = 1.f / fmaxf(sqrtf(ss2), 1e-12f);
    pa.x*=inv2; pa.y*=inv2; pa.z*=inv2; pa.w*=inv2;
    ((float4*)(Pa + ((size_t)b * NWAY + c) * DD))[t] = pa;
}

// cross-modal guidance + per-step logits/CE (+argmax acc on last layer)
__global__ __launch_bounds__(256) void k_guide(
    float* __restrict__ V, const float* __restrict__ Pa,
    const float* __restrict__ betaPtr, const int* __restrict__ qy, int layer)
{
    __shared__ float sPa[NWAY * DD];
    __shared__ float sV[DD];
    __shared__ float sims[NWAY];
    __shared__ float soft[NWAY];
    __shared__ float red[8];
    __shared__ float sInv;
    int b = blockIdx.x, chunk = blockIdx.y;
    int tid = threadIdx.x;
    float beta = *betaPtr;
    const float* PaB = Pa + (size_t)b * NWAY * DD;
    for (int i = tid; i < NWAY * DD; i += 256) sPa[i] = PaB[i];
    __syncthreads();
    int warp = tid >> 5, lane = tid & 31;
    float localLoss = 0.f; int localAcc = 0;
    for (int n = chunk * ROWS_PER_CHUNK; n < chunk * ROWS_PER_CHUNK + ROWS_PER_CHUNK; n++) {
        float* Vrow = V + ((size_t)b * NTOT + n) * DD;
        for (int i = tid; i < DD; i += 256) sV[i] = Vrow[i];
        __syncthreads();
        for (int m = warp; m < NWAY; m += 8) {
            float d = 0.f;
            for (int i = lane; i < DD; i += 32) d += sV[i] * sPa[m * DD + i];
            #pragma unroll
            for (int off = 16; off; off >>= 1) d += __shfl_down_sync(0xffffffffu, d, off);
            if (lane == 0) sims[m] = d;
        }
        __syncthreads();
        if (tid == 0) {
            float mx = -1e30f;
            for (int m = 0; m < NWAY; m++) mx = fmaxf(mx, sims[m]);
            float s = 0.f;
            for (int m = 0; m < NWAY; m++) { float e = expf((sims[m] - mx) * TAUINV); soft[m] = e; s += e; }
            float inv = 1.f / s;
            for (int m = 0; m < NWAY; m++) soft[m] *= inv;
        }
        __syncthreads();
        int d0 = tid, d1 = tid + 256;
        float g0 = 0.f, g1 = 0.f;
        #pragma unroll
        for (int m = 0; m < NWAY; m++) {
            g0 += soft[m] * sPa[m * DD + d0];
            g1 += soft[m] * sPa[m * DD + d1];
        }
        float nv0 = beta * sV[d0] + (1.f - beta) * g0;
        float nv1 = beta * sV[d1] + (1.f - beta) * g1;
        float ss = nv0 * nv0 + nv1 * nv1;
        ss = blockSum(ss, red);
        if (tid == 0) sInv = 1.f / fmaxf(sqrtf(ss), 1e-12f);
        __syncthreads();
        nv0 *= sInv; nv1 *= sInv;
        Vrow[d0] = nv0; Vrow[d1] = nv1;
        sV[d0] = nv0; sV[d1] = nv1;
        __syncthreads();
        if (n >= NKQ) {
            for (int m = warp; m < NWAY; m += 8) {
                float d = 0.f;
                for (int i = lane; i < DD; i += 32) d += sV[i] * sPa[m * DD + i];
                #pragma unroll
                for (int off = 16; off; off >>= 1) d += __shfl_down_sync(0xffffffffu, d, off);
                if (lane == 0) sims[m] = 5.0f * d;   // LOGIT_SCALE
            }
            __syncthreads();
            if (tid == 0) {
                float mx = -1e30f; int am = 0;
                for (int m = 0; m < NWAY; m++) if (sims[m] > mx) { mx = sims[m]; am = m; }
                float s = 0.f;
                for (int m = 0; m < NWAY; m++) s += expf(sims[m] - mx);
                float lse = mx + logf(s);
                int lbl = qy[b * QN + (n - NKQ)];
                localLoss += lse - sims[lbl];
                if (layer == LL - 1) localAcc += (am == lbl) ? 1 : 0;
            }
            __syncthreads();
        }
    }
    if (tid == 0) {
        int pi = b * CHUNKS + chunk;
        g_lossP[pi] += localLoss;
        if (layer == LL - 1) g_accP[pi] = localAcc;
    }
}

__global__ void k_final(float* __restrict__ out) {
    __shared__ float red[8];
    int t = threadIdx.x;  // 256
    float ls = 0.f; float ac = 0.f;
    for (int i = t; i < BB * CHUNKS; i += 256) { ls += g_lossP[i]; ac += (float)g_accP[i]; }
    float L = blockSum(ls, red);
    float A = blockSum(ac, red);
    if (t == 0) {
        out[0] = L / (float)(BB * QN * LL);
        out[1] = A / (float)(BB * QN);
    }
}

// ---------------- launch ----------------
extern "C" void kernel_launch(void* const* d_in, const int* in_sizes, int n_in,
                              void* d_out, int out_size)
{
    const float* V_feat = (const float*)d_in[0];
    const float* P_feat = (const float*)d_in[1];
    const int*   qy     = (const int*)  d_in[2];
    const float* igbW   = (const float*)d_in[3];
    const float* igbB   = (const float*)d_in[4];
    const float* igbS   = (const float*)d_in[5];
    const float* pgbW   = (const float*)d_in[6];
    const float* pgbB   = (const float*)d_in[7];
    const float* pgbS   = (const float*)d_in[8];
    const float* alpha  = (const float*)d_in[9];
    const float* beta   = (const float*)d_in[10];
    float* out = (float*)d_out;

    float *pV, *pV0, *pMsg, *pGemm, *pP, *pP0, *pPmsg, *pPgemm, *pPa, *pSim, *pW;
    int *pIdx;
    cudaGetSymbolAddress((void**)&pV,    g_V);
    cudaGetSymbolAddress((void**)&pV0,   g_V0);
    cudaGetSymbolAddress((void**)&pMsg,  g_msg);
    cudaGetSymbolAddress((void**)&pGemm, g_gemm);
    cudaGetSymbolAddress((void**)&pP,    g_P);
    cudaGetSymbolAddress((void**)&pP0,   g_P0);
    cudaGetSymbolAddress((void**)&pPmsg, g_Pmsg);
    cudaGetSymbolAddress((void**)&pPgemm,g_Pgemm);
    cudaGetSymbolAddress((void**)&pPa,   g_Pa);
    cudaGetSymbolAddress((void**)&pSim,  g_sim);
    cudaGetSymbolAddress((void**)&pW,    g_w);
    cudaGetSymbolAddress((void**)&pIdx,  g_idx);

    k_zero<<<(BB * CHUNKS + 255) / 256, 256>>>();
    k_init<<<BB * NTOT, 128>>>(V_feat, pV, pV0);
    k_init<<<BB * NWAY, 128>>>(P_feat, pP, pP0);

    for (int i = 0; i < LL; i++) {
        // ---- instance branch ----
        {
            dim3 gs((NTOT + 63) / 64, (NTOT + 63) / 64, BB);
            k_gemm_bf<64, 64, 2, 2><<<gs, 128>>>(pV, pV, pSim, NTOT, NTOT, DD,
                                   (size_t)NTOT * DD, (size_t)NTOT * DD, (size_t)NTOT * NTOT);
        }
        k_topk<<<(BB * NTOT + 3) / 4, 128>>>(pSim, NTOT, BB * NTOT, pIdx, pW);
        k_gather<<<BB * NTOT, 128>>>(pV, pIdx, pW, pMsg, NTOT);
        {
            dim3 gs(DD / 128, (BB * NTOT) / 128, 1);
            k_gemm_bf<128, 128, 2, 4><<<gs, 256>>>(pMsg, igbW + (size_t)i * DD * DD, pGemm,
                                   BB * NTOT, DD, DD, 0, 0, 0);
        }
        k_epi<<<BB * NTOT, 128>>>(pV, pV0, pGemm, igbB + (size_t)i * DD, igbS, i);
        // ---- prototype branch (fused sim/topk/gather) ----
        k_proto<<<BB, 256>>>(pP, pPmsg);
        {
            dim3 gs(DD / 128, (BB * NWAY) / 128, 1);
            k_gemm_bf<128, 128, 2, 4><<<gs, 256>>>(pPmsg, pgbW + (size_t)i * DD * DD, pPgemm,
                                   BB * NWAY, DD, DD, 0, 0, 0);
        }
        k_epi<<<BB * NWAY, 128>>>(pP, pP0, pPgemm, pgbB + (size_t)i * DD, pgbS, i);
        // ---- centers, adapted prototypes, guidance + logits/CE ----
        k_vc_pa<<<dim3(BB, NWAY), 128>>>(pV, pP, pPa, alpha);
        k_guide<<<dim3(BB, CHUNKS), 256>>>(pV, pPa, beta, qy, i);
    }
    k_final<<<1, 256>>>(out);
}

// round 5
// speedup vs baseline: 2.4776x; 1.3877x over previous
#include <cuda_runtime.h>
#include <cuda_bf16.h>
#include <math.h>
#include <stdint.h>

// ---------------- problem constants ----------------
#define BB    256
#define NTOT  175
#define NPAD  192     // padded rows for V bf16 arrays (multiple of 64)
#define NWAY  20
#define NWPAD 64      // padded Pa rows
#define KSHOT 5
#define QN    75
#define DD    512
#define LL    4
#define KNEI  5
#define TAUINV 10.0f
#define NKQ   (NWAY*KSHOT)

// ---------------- device scratch ----------------
__device__ float g_V   [(size_t)BB*NTOT*DD];
__device__ float g_V0  [(size_t)BB*NTOT*DD];
__device__ __nv_bfloat16 g_Vh[(size_t)BB*NPAD*DD];
__device__ __nv_bfloat16 g_Vl[(size_t)BB*NPAD*DD];
__device__ __nv_bfloat16 g_Mh[(size_t)BB*NTOT*DD];
__device__ __nv_bfloat16 g_Ml[(size_t)BB*NTOT*DD];
__device__ float g_gemm[(size_t)BB*NTOT*DD];
__device__ float g_P    [(size_t)BB*NWAY*DD];
__device__ float g_P0   [(size_t)BB*NWAY*DD];
__device__ __nv_bfloat16 g_PMh[(size_t)BB*NWAY*DD];
__device__ __nv_bfloat16 g_PMl[(size_t)BB*NWAY*DD];
__device__ float g_Pgemm[(size_t)BB*NWAY*DD];
__device__ float g_Pa   [(size_t)BB*NWAY*DD];
__device__ __nv_bfloat16 g_Pah[(size_t)BB*NWPAD*DD];
__device__ __nv_bfloat16 g_Pal[(size_t)BB*NWPAD*DD];
__device__ float g_sim [(size_t)BB*NTOT*NTOT];
__device__ float g_simQ[(size_t)BB*NPAD*NWPAD];
__device__ float g_G   [(size_t)BB*NWAY*NWAY];
__device__ __nv_bfloat16 g_iWh[(size_t)LL*DD*DD];
__device__ __nv_bfloat16 g_iWl[(size_t)LL*DD*DD];
__device__ __nv_bfloat16 g_pWh[(size_t)LL*DD*DD];
__device__ __nv_bfloat16 g_pWl[(size_t)LL*DD*DD];
__device__ int   g_idx [(size_t)BB*NTOT*KNEI];
__device__ float g_w   [(size_t)BB*NTOT*KNEI];
__device__ float g_lossP[BB*32];
__device__ int   g_accP [BB*32];

// ---------------- helpers ----------------
__device__ __forceinline__ float blockSum(float v, float* red) {
    int tid = threadIdx.x;
    #pragma unroll
    for (int off = 16; off; off >>= 1) v += __shfl_down_sync(0xffffffffu, v, off);
    if ((tid & 31) == 0) red[tid >> 5] = v;
    __syncthreads();
    float r = 0.f;
    int nw = blockDim.x >> 5;
    if (tid < 32) {
        if (tid < nw) r = red[tid];
        #pragma unroll
        for (int off = 16; off; off >>= 1) r += __shfl_down_sync(0xffffffffu, r, off);
        if (tid == 0) red[0] = r;
    }
    __syncthreads();
    r = red[0];
    __syncthreads();
    return r;
}

__device__ __forceinline__ float warpSum(float v) {
    #pragma unroll
    for (int off = 16; off; off >>= 1) v += __shfl_xor_sync(0xffffffffu, v, off);
    return v;
}

__device__ __forceinline__ uint32_t smem_u32(const void* p) {
    return (uint32_t)__cvta_generic_to_shared(p);
}

__device__ __forceinline__ void cpasync16(uint32_t dst, const void* src) {
    asm volatile("cp.async.ca.shared.global [%0], [%1], 16;" :: "r"(dst), "l"(src));
}
__device__ __forceinline__ void cpcommit() { asm volatile("cp.async.commit_group;"); }
__device__ __forceinline__ void cpwait0()  { asm volatile("cp.async.wait_group 0;"); }

__device__ __forceinline__ void ldsm4(uint32_t& r0, uint32_t& r1, uint32_t& r2, uint32_t& r3,
                                      uint32_t addr) {
    asm volatile("ldmatrix.sync.aligned.m8n8.x4.shared.b16 {%0,%1,%2,%3}, [%4];"
                 : "=r"(r0), "=r"(r1), "=r"(r2), "=r"(r3) : "r"(addr));
}

__device__ __forceinline__ void mma16(float* c, const uint32_t* a, const uint32_t* b) {
    asm volatile(
        "mma.sync.aligned.m16n8k16.row.col.f32.bf16.bf16.f32 "
        "{%0,%1,%2,%3}, {%4,%5,%6,%7}, {%8,%9}, {%0,%1,%2,%3};"
        : "+f"(c[0]), "+f"(c[1]), "+f"(c[2]), "+f"(c[3])
        : "r"(a[0]), "r"(a[1]), "r"(a[2]), "r"(a[3]), "r"(b[0]), "r"(b[1]));
}

__device__ __forceinline__ void split1(float x, __nv_bfloat16& h, __nv_bfloat16& l) {
    h = __float2bfloat16(x);
    l = __float2bfloat16(x - __bfloat162float(h));
}
// split float4 into two 8-byte packed (4x bf16) values
__device__ __forceinline__ void split4(float4 v, uint2& hv, uint2& lv) {
    __nv_bfloat16 h0,h1,h2,h3,l0,l1,l2,l3;
    split1(v.x,h0,l0); split1(v.y,h1,l1); split1(v.z,h2,l2); split1(v.w,h3,l3);
    hv.x = (uint32_t)__bfloat16_as_ushort(h0) | ((uint32_t)__bfloat16_as_ushort(h1) << 16);
    hv.y = (uint32_t)__bfloat16_as_ushort(h2) | ((uint32_t)__bfloat16_as_ushort(h3) << 16);
    lv.x = (uint32_t)__bfloat16_as_ushort(l0) | ((uint32_t)__bfloat16_as_ushort(l1) << 16);
    lv.y = (uint32_t)__bfloat16_as_ushort(l2) | ((uint32_t)__bfloat16_as_ushort(l3) << 16);
}

// ---------------- small kernels ----------------

__global__ void k_zero() {
    int i = blockIdx.x * 256 + threadIdx.x;
    if (i < BB * 32) { g_lossP[i] = 0.f; g_accP[i] = 0; }
}

__global__ void k_splitW(const float* __restrict__ src, __nv_bfloat16* __restrict__ h,
                         __nv_bfloat16* __restrict__ l, int n) {
    int i = blockIdx.x * 256 + threadIdx.x;
    if (i < n) { __nv_bfloat16 hh, ll; split1(src[i], hh, ll); h[i] = hh; l[i] = ll; }
}

__global__ void k_padV(__nv_bfloat16* __restrict__ Vh, __nv_bfloat16* __restrict__ Vl) {
    int b = blockIdx.x / (NPAD - NTOT);
    int r = NTOT + blockIdx.x % (NPAD - NTOT);
    size_t off = ((size_t)b * NPAD + r) * DD;
    int t = threadIdx.x;  // 128
    ((uint2*)(Vh + off))[t] = make_uint2(0, 0);
    ((uint2*)(Vl + off))[t] = make_uint2(0, 0);
}

// l2-normalize; optionally also emit bf16 hi/lo into padded array
__global__ void k_init(const float* __restrict__ in, float* __restrict__ out,
                       float* __restrict__ out0, __nv_bfloat16* __restrict__ oh,
                       __nv_bfloat16* __restrict__ ol, int rowsPerB, int padStride) {
    __shared__ float red[8];
    int row = blockIdx.x;
    int t = threadIdx.x;  // 128
    float4 v = ((const float4*)(in + (size_t)row * DD))[t];
    float ss = v.x*v.x + v.y*v.y + v.z*v.z + v.w*v.w;
    ss = blockSum(ss, red);
    float inv = 1.f / fmaxf(sqrtf(ss), 1e-12f);
    float4 o = make_float4(v.x*inv, v.y*inv, v.z*inv, v.w*inv);
    ((float4*)(out  + (size_t)row * DD))[t] = o;
    ((float4*)(out0 + (size_t)row * DD))[t] = o;
    if (oh) {
        int b = row / rowsPerB, n = row % rowsPerB;
        size_t po = ((size_t)b * padStride + n) * DD;
        uint2 hv, lv; split4(o, hv, lv);
        ((uint2*)(oh + po))[t] = hv;
        ((uint2*)(ol + po))[t] = lv;
    }
}

// ============== bf16 hi/lo split tensor-core NT GEMM (cp.async pipeline) ==============
// C[m,n] = sum_k A[m,k]*B[n,k], fp32-equivalent via Ah*Bh + Ah*Bl + Al*Bh. K = 512 fixed.
// 64x64 tile, BK=32, 128 threads (2x2 warps), double-buffered cp.async,
// smem rows padded to 80B -> conflict-free ldmatrix.
#define GSTG 20480   // 4 arrays * 5120 bytes
__global__ __launch_bounds__(128) void k_gemm_bf(
    const __nv_bfloat16* __restrict__ Ah, const __nv_bfloat16* __restrict__ Al,
    const __nv_bfloat16* __restrict__ Bh, const __nv_bfloat16* __restrict__ Bl,
    float* __restrict__ C, int M, int N, int ldc,
    size_t strA, size_t strB, size_t strC)
{
    __shared__ __align__(16) uint8_t smem[2][4][64 * 80];

    int tid = threadIdx.x;
    int m0 = blockIdx.y * 64, n0 = blockIdx.x * 64;
    const __nv_bfloat16* pAh = Ah + (size_t)blockIdx.z * strA + (size_t)m0 * DD;
    const __nv_bfloat16* pAl = Al + (size_t)blockIdx.z * strA + (size_t)m0 * DD;
    const __nv_bfloat16* pBh = Bh + (size_t)blockIdx.z * strB + (size_t)n0 * DD;
    const __nv_bfloat16* pBl = Bl + (size_t)blockIdx.z * strB + (size_t)n0 * DD;
    float* Cb = C + (size_t)blockIdx.z * strC;

    int warp = tid >> 5, lane = tid & 31;
    int warpM = warp >> 1, warpN = warp & 1;
    int j = lane >> 3, r8 = lane & 7;

    uint32_t offA[2], offB[2];
    #pragma unroll
    for (int mt = 0; mt < 2; mt++) {
        int row = warpM * 32 + mt * 16 + (j & 1) * 8 + r8;
        offA[mt] = (uint32_t)(row * 80 + (j >> 1) * 16);
    }
    #pragma unroll
    for (int nt2 = 0; nt2 < 2; nt2++) {
        int n = warpN * 32 + nt2 * 16 + (j >> 1) * 8 + r8;
        offB[nt2] = (uint32_t)(n * 80 + (j & 1) * 16);
    }
    uint32_t sbase = smem_u32(&smem[0][0][0]);

    float acc[2][4][4];
    #pragma unroll
    for (int mt = 0; mt < 2; mt++)
        #pragma unroll
        for (int nt = 0; nt < 4; nt++)
            #pragma unroll
            for (int r = 0; r < 4; r++) acc[mt][nt][r] = 0.f;

    // staging map: 8 cp.async per thread per stage
    int cIdx0 = tid, cIdx1 = tid + 128;
    int r0s = cIdx0 >> 2, c0s = cIdx0 & 3;
    int r1s = cIdx1 >> 2, c1s = cIdx1 & 3;

    auto issue = [&](int st, int kg) {
        uint32_t sb = sbase + st * GSTG;
        cpasync16(sb +           r0s*80 + c0s*16, pAh + (size_t)r0s*DD + kg + c0s*8);
        cpasync16(sb +           r1s*80 + c1s*16, pAh + (size_t)r1s*DD + kg + c1s*8);
        cpasync16(sb + 5120   +  r0s*80 + c0s*16, pAl + (size_t)r0s*DD + kg + c0s*8);
        cpasync16(sb + 5120   +  r1s*80 + c1s*16, pAl + (size_t)r1s*DD + kg + c1s*8);
        cpasync16(sb + 10240  +  r0s*80 + c0s*16, pBh + (size_t)r0s*DD + kg + c0s*8);
        cpasync16(sb + 10240  +  r1s*80 + c1s*16, pBh + (size_t)r1s*DD + kg + c1s*8);
        cpasync16(sb + 15360  +  r0s*80 + c0s*16, pBl + (size_t)r0s*DD + kg + c0s*8);
        cpasync16(sb + 15360  +  r1s*80 + c1s*16, pBl + (size_t)r1s*DD + kg + c1s*8);
        cpcommit();
    };

    issue(0, 0);
    int buf = 0;
    const int iters = DD / 32;   // 16
    for (int it = 0; it < iters; it++) {
        cpwait0();
        __syncthreads();
        if (it + 1 < iters) issue(buf ^ 1, (it + 1) * 32);
        uint32_t sb = sbase + buf * GSTG;
        #pragma unroll
        for (int s = 0; s < 2; s++) {
            uint32_t so = s * 32;
            uint32_t ah[2][4], al[2][4], bh[4][2], bl[4][2];
            #pragma unroll
            for (int mt = 0; mt < 2; mt++) {
                ldsm4(ah[mt][0], ah[mt][1], ah[mt][2], ah[mt][3], sb + offA[mt] + so);
                ldsm4(al[mt][0], al[mt][1], al[mt][2], al[mt][3], sb + 5120 + offA[mt] + so);
            }
            #pragma unroll
            for (int nt2 = 0; nt2 < 2; nt2++) {
                uint32_t q0,q1,q2,q3;
                ldsm4(q0,q1,q2,q3, sb + 10240 + offB[nt2] + so);
                bh[nt2*2][0]=q0; bh[nt2*2][1]=q1; bh[nt2*2+1][0]=q2; bh[nt2*2+1][1]=q3;
                ldsm4(q0,q1,q2,q3, sb + 15360 + offB[nt2] + so);
                bl[nt2*2][0]=q0; bl[nt2*2][1]=q1; bl[nt2*2+1][0]=q2; bl[nt2*2+1][1]=q3;
            }
            #pragma unroll
            for (int mt = 0; mt < 2; mt++)
                #pragma unroll
                for (int nt = 0; nt < 4; nt++) {
                    mma16(acc[mt][nt], ah[mt], bh[nt]);
                    mma16(acc[mt][nt], ah[mt], bl[nt]);
                    mma16(acc[mt][nt], al[mt], bh[nt]);
                }
        }
        buf ^= 1;
    }

    #pragma unroll
    for (int mt = 0; mt < 2; mt++) {
        #pragma unroll
        for (int nt = 0; nt < 4; nt++) {
            int row = m0 + warpM * 32 + mt * 16 + (lane >> 2);
            int col = n0 + warpN * 32 + nt * 8 + (lane & 3) * 2;
            if (row < M) {
                if (col < N)     Cb[(size_t)row * ldc + col]     = acc[mt][nt][0];
                if (col + 1 < N) Cb[(size_t)row * ldc + col + 1] = acc[mt][nt][1];
            }
            if (row + 8 < M) {
                if (col < N)     Cb[(size_t)(row + 8) * ldc + col]     = acc[mt][nt][2];
                if (col + 1 < N) Cb[(size_t)(row + 8) * ldc + col + 1] = acc[mt][nt][3];
            }
        }
    }
}

// per-row top-KNEI + softmax; one warp per row
__global__ void k_topk(const float* __restrict__ sim, int nCols, int totalRows,
                       int* __restrict__ idxOut, float* __restrict__ wOut)
{
    int row = blockIdx.x * 4 + (threadIdx.x >> 5);
    if (row >= totalRows) return;
    int lane = threadIdx.x & 31;
    const float* sr = sim + (size_t)row * nCols;
    float v[6];
    #pragma unroll
    for (int jj = 0; jj < 6; jj++) {
        int c = lane + jj * 32;
        v[jj] = (c < nCols) ? sr[c] : -INFINITY;
    }
    float cv[KNEI]; int ci[KNEI];
    #pragma unroll
    for (int p = 0; p < KNEI; p++) {
        float bv = -INFINITY; int bc = 0x7fffffff;
        #pragma unroll
        for (int jj = 0; jj < 6; jj++)
            if (v[jj] > bv) { bv = v[jj]; bc = lane + jj * 32; }
        #pragma unroll
        for (int off = 16; off; off >>= 1) {
            float ov = __shfl_down_sync(0xffffffffu, bv, off);
            int   oc = __shfl_down_sync(0xffffffffu, bc, off);
            if (ov > bv || (ov == bv && oc < bc)) { bv = ov; bc = oc; }
        }
        bv = __shfl_sync(0xffffffffu, bv, 0);
        bc = __shfl_sync(0xffffffffu, bc, 0);
        cv[p] = bv; ci[p] = bc;
        if ((bc & 31) == lane) v[bc >> 5] = -INFINITY;
    }
    if (lane == 0) {
        float mx = cv[0], e[KNEI], s = 0.f;
        #pragma unroll
        for (int p = 0; p < KNEI; p++) { e[p] = expf((cv[p] - mx) * TAUINV); s += e[p]; }
        float inv = 1.f / s;
        #pragma unroll
        for (int p = 0; p < KNEI; p++) {
            idxOut[(size_t)row * KNEI + p] = ci[p];
            wOut [(size_t)row * KNEI + p] = e[p] * inv;
        }
    }
}

// msg = sparse adj @ V -> bf16 hi/lo
__global__ void k_gather(const float* __restrict__ src, const int* __restrict__ idx,
                         const float* __restrict__ w, __nv_bfloat16* __restrict__ mh,
                         __nv_bfloat16* __restrict__ ml, int rowsPerB)
{
    int row = blockIdx.x;
    int b = row / rowsPerB;
    const int*   ir = idx + (size_t)row * KNEI;
    const float* wr = w   + (size_t)row * KNEI;
    int ji[KNEI]; float wj[KNEI];
    #pragma unroll
    for (int p = 0; p < KNEI; p++) { ji[p] = ir[p]; wj[p] = wr[p]; }
    const float* base = src + (size_t)b * rowsPerB * DD;
    int t = threadIdx.x;   // 128
    float4 acc = make_float4(0,0,0,0);
    #pragma unroll
    for (int p = 0; p < KNEI; p++) {
        float4 x = ((const float4*)(base + (size_t)ji[p] * DD))[t];
        acc.x += wj[p]*x.x; acc.y += wj[p]*x.y; acc.z += wj[p]*x.z; acc.w += wj[p]*x.w;
    }
    uint2 hv, lv; split4(acc, hv, lv);
    ((uint2*)(mh + (size_t)row * DD))[t] = hv;
    ((uint2*)(ml + (size_t)row * DD))[t] = lv;
}

// fused prototype branch: sims + top-5 softmax + gather -> PMsg hi/lo
__global__ __launch_bounds__(256) void k_proto(const float* __restrict__ P,
                                               __nv_bfloat16* __restrict__ mh,
                                               __nv_bfloat16* __restrict__ ml)
{
    __shared__ float sP[NWAY * DD];
    __shared__ float sSim[NWAY][NWAY];
    __shared__ float sW[NWAY][KNEI];
    __shared__ int   sI[NWAY][KNEI];
    int b = blockIdx.x, tid = threadIdx.x;
    const float* Pb = P + (size_t)b * NWAY * DD;
    for (int i = tid; i < NWAY * DD; i += 256) sP[i] = Pb[i];
    __syncthreads();
    int warp = tid >> 5, lane = tid & 31;
    for (int p = warp; p < NWAY * NWAY; p += 8) {
        int r = p / NWAY, c = p % NWAY;
        float d = 0.f;
        for (int i = lane; i < DD; i += 32) d += sP[r * DD + i] * sP[c * DD + i];
        d = warpSum(d);
        if (lane == 0) sSim[r][c] = d;
    }
    __syncthreads();
    if (tid < NWAY) {
        float v[NWAY];
        #pragma unroll
        for (int c = 0; c < NWAY; c++) v[c] = sSim[tid][c];
        float cv[KNEI]; int ci[KNEI];
        #pragma unroll
        for (int p = 0; p < KNEI; p++) {
            float bv = -INFINITY; int bc = 0;
            #pragma unroll
            for (int c = 0; c < NWAY; c++)
                if (v[c] > bv) { bv = v[c]; bc = c; }
            cv[p] = bv; ci[p] = bc; v[bc] = -INFINITY;
        }
        float mx = cv[0], e[KNEI], s = 0.f;
        #pragma unroll
        for (int p = 0; p < KNEI; p++) { e[p] = expf((cv[p] - mx) * TAUINV); s += e[p]; }
        float inv = 1.f / s;
        #pragma unroll
        for (int p = 0; p < KNEI; p++) { sW[tid][p] = e[p] * inv; sI[tid][p] = ci[p]; }
    }
    __syncthreads();
    size_t base = (size_t)b * NWAY * DD;
    for (int e = tid; e < NWAY * DD; e += 256) {
        int r = e >> 9, d = e & (DD - 1);
        float a = 0.f;
        #pragma unroll
        for (int p = 0; p < KNEI; p++) a += sW[r][p] * sP[sI[r][p] * DD + d];
        __nv_bfloat16 hh, llv; split1(a, hh, llv);
        mh[base + e] = hh; ml[base + e] = llv;
    }
}

// x = l2n(0.8*(x + s*tanh(G + bias)) + 0.2*x0); optionally emit bf16 hi/lo (padded)
__global__ void k_epi(float* __restrict__ X, const float* __restrict__ X0,
                      const float* __restrict__ G, const float* __restrict__ bias,
                      const float* __restrict__ scaleArr, int layer,
                      __nv_bfloat16* __restrict__ oh, __nv_bfloat16* __restrict__ ol,
                      int rowsPerB, int padStride)
{
    __shared__ float red[8];
    int row = blockIdx.x;
    float s = scaleArr[layer];
    int t = threadIdx.x;  // 128
    float4 vv = ((const float4*)(X  + (size_t)row * DD))[t];
    float4 gg = ((const float4*)(G  + (size_t)row * DD))[t];
    float4 bb = ((const float4*)(bias))[t];
    float4 v0 = ((const float4*)(X0 + (size_t)row * DD))[t];
    float4 r4;
    r4.x = 0.8f*(vv.x + s*tanhf(gg.x + bb.x)) + 0.2f*v0.x;
    r4.y = 0.8f*(vv.y + s*tanhf(gg.y + bb.y)) + 0.2f*v0.y;
    r4.z = 0.8f*(vv.z + s*tanhf(gg.z + bb.z)) + 0.2f*v0.z;
    r4.w = 0.8f*(vv.w + s*tanhf(gg.w + bb.w)) + 0.2f*v0.w;
    float ss = r4.x*r4.x + r4.y*r4.y + r4.z*r4.z + r4.w*r4.w;
    ss = blockSum(ss, red);
    float inv = 1.f / fmaxf(sqrtf(ss), 1e-12f);
    r4.x*=inv; r4.y*=inv; r4.z*=inv; r4.w*=inv;
    ((float4*)(X + (size_t)row * DD))[t] = r4;
    if (oh) {   // refresh bf16 hi/lo mirror (CRITICAL: simsQ GEMM consumes this)
        int b = row / rowsPerB, n = row % rowsPerB;
        size_t po = ((size_t)b * padStride + n) * DD;
        uint2 hv, lv; split4(r4, hv, lv);
        ((uint2*)(oh + po))[t] = hv;
        ((uint2*)(ol + po))[t] = lv;
    }
}

// VC + Pa (f32 + bf16 hi/lo with zero padding rows)
__global__ void k_vc_pa(const float* __restrict__ V, const float* __restrict__ P,
                        float* __restrict__ Pa, __nv_bfloat16* __restrict__ Pah,
                        __nv_bfloat16* __restrict__ Pal, const float* __restrict__ alphaPtr)
{
    __shared__ float red[8];
    int b = blockIdx.x, c = blockIdx.y;
    int t = threadIdx.x;  // 128
    if (c >= NWAY) {   // zero pad rows of Pah/Pal
        size_t po = ((size_t)b * NWPAD + c) * DD;
        ((uint2*)(Pah + po))[t] = make_uint2(0, 0);
        ((uint2*)(Pal + po))[t] = make_uint2(0, 0);
        return;
    }
    const float* base = V + ((size_t)b * NTOT + (size_t)c * KSHOT) * DD;
    float4 s4 = make_float4(0,0,0,0);
    #pragma unroll
    for (int k = 0; k < KSHOT; k++) {
        float4 x = ((const float4*)(base + (size_t)k * DD))[t];
        s4.x += x.x; s4.y += x.y; s4.z += x.z; s4.w += x.w;
    }
    s4.x *= 0.2f; s4.y *= 0.2f; s4.z *= 0.2f; s4.w *= 0.2f;
    float ss = s4.x*s4.x + s4.y*s4.y + s4.z*s4.z + s4.w*s4.w;
    ss = blockSum(ss, red);
    float inv = 1.f / fmaxf(sqrtf(ss), 1e-12f);
    float a = *alphaPtr;
    float4 p4 = ((const float4*)(P + ((size_t)b * NWAY + c) * DD))[t];
    float4 pa;
    pa.x = a*p4.x + (1.f-a)*s4.x*inv;
    pa.y = a*p4.y + (1.f-a)*s4.y*inv;
    pa.z = a*p4.z + (1.f-a)*s4.z*inv;
    pa.w = a*p4.w + (1.f-a)*s4.w*inv;
    float ss2 = pa.x*pa.x + pa.y*pa.y + pa.z*pa.z + pa.w*pa.w;
    ss2 = blockSum(ss2, red);
    float inv2 = 1.f / fmaxf(sqrtf(ss2), 1e-12f);
    pa.x*=inv2; pa.y*=inv2; pa.z*=inv2; pa.w*=inv2;
    ((float4*)(Pa + ((size_t)b * NWAY + c) * DD))[t] = pa;
    size_t po = ((size_t)b * NWPAD + c) * DD;
    uint2 hv, lv; split4(pa, hv, lv);
    ((uint2*)(Pah + po))[t] = hv;
    ((uint2*)(Pal + po))[t] = lv;
}

// Gram matrix G = Pa . Pa^T (20x20 per batch)
__global__ __launch_bounds__(256) void k_gram(const float* __restrict__ Pa,
                                              float* __restrict__ G)
{
    __shared__ float sP[NWAY * DD];
    int b = blockIdx.x, tid = threadIdx.x;
    const float* Pb = Pa + (size_t)b * NWAY * DD;
    for (int i = tid; i < NWAY * DD; i += 256) sP[i] = Pb[i];
    __syncthreads();
    int w = tid >> 5, lane = tid & 31;
    for (int p = w; p < NWAY * NWAY; p += 8) {
        int i = p / NWAY, jc = p % NWAY;
        float d = 0.f;
        for (int k = lane; k < DD; k += 32) d += sP[i * DD + k] * sP[jc * DD + k];
        d = warpSum(d);
        if (lane == 0) G[(size_t)b * NWAY * NWAY + p] = d;
    }
}

// warp-per-row guidance: softmax(sims), V' update, Gram-based logits/CE/acc
__global__ __launch_bounds__(256) void k_guide2(
    float* __restrict__ V, __nv_bfloat16* __restrict__ Vh, __nv_bfloat16* __restrict__ Vl,
    const float* __restrict__ Pa, const float* __restrict__ G,
    const float* __restrict__ simsQ, const float* __restrict__ betaPtr,
    const int* __restrict__ qy, int layer)
{
    __shared__ float sPa[NWAY * DD];
    __shared__ float sG[NWAY * NWAY];
    __shared__ float sSoft[8][NWAY];
    int b = blockIdx.x;
    int tid = threadIdx.x, w = tid >> 5, lane = tid & 31;
    float beta = *betaPtr;
    const float* PaB = Pa + (size_t)b * NWAY * DD;
    for (int i = tid; i < NWAY * DD; i += 256) sPa[i] = PaB[i];
    for (int i = tid; i < NWAY * NWAY; i += 256) sG[i] = G[(size_t)b * NWAY * NWAY + i];
    __syncthreads();
    int gw = blockIdx.y * 8 + w;   // 0..31
    float localLoss = 0.f; int localAcc = 0;
    for (int r = gw; r < NTOT; r += 32) {
        float s = (lane < NWAY) ? simsQ[((size_t)b * NPAD + r) * NWPAD + lane] : -INFINITY;
        float mx = s;
        #pragma unroll
        for (int off = 16; off; off >>= 1) mx = fmaxf(mx, __shfl_xor_sync(0xffffffffu, mx, off));
        float e = (lane < NWAY) ? expf((s - mx) * TAUINV) : 0.f;
        float sum = warpSum(e);
        float soft = e / sum;
        if (lane < NWAY) sSoft[w][lane] = soft;
        __syncwarp();
        // t_j = (G soft)_j and scalar norm
        float tj = 0.f;
        if (lane < NWAY) {
            #pragma unroll
            for (int m = 0; m < NWAY; m++) tj += sSoft[w][m] * sG[m * NWAY + lane];
        }
        float ob = 1.f - beta;
        float contrib = (lane < NWAY) ? soft * (2.f * beta * ob * s + ob * ob * tj) : 0.f;
        float n2 = beta * beta + warpSum(contrib);
        float invn = 1.f / fmaxf(sqrtf(n2), 1e-12f);
        // V' update in d-space
        float* Vrow = V + ((size_t)b * NTOT + r) * DD;
        __nv_bfloat16* VhRow = Vh + ((size_t)b * NPAD + r) * DD;
        __nv_bfloat16* VlRow = Vl + ((size_t)b * NPAD + r) * DD;
        #pragma unroll
        for (int i = 0; i < 16; i++) {
            int d = lane + 32 * i;
            float g = 0.f;
            #pragma unroll
            for (int m = 0; m < NWAY; m++) g += sSoft[w][m] * sPa[m * DD + d];
            float nv = (beta * Vrow[d] + ob * g) * invn;
            Vrow[d] = nv;
            __nv_bfloat16 hh, ll; split1(nv, hh, ll);
            VhRow[d] = hh; VlRow[d] = ll;
        }
        if (r >= NKQ) {
            float logit = (lane < NWAY) ? 5.f * invn * (beta * s + ob * tj) : -INFINITY;
            float m2 = logit;
            #pragma unroll
            for (int off = 16; off; off >>= 1) m2 = fmaxf(m2, __shfl_xor_sync(0xffffffffu, m2, off));
            float ee = (lane < NWAY) ? expf(logit - m2) : 0.f;
            float ssum = warpSum(ee);
            float lse = m2 + logf(ssum);
            int lbl = qy[b * QN + (r - NKQ)];
            float ll = __shfl_sync(0xffffffffu, logit, lbl);
            if (lane == 0) localLoss += lse - ll;
            if (layer == LL - 1) {
                float bv = logit; int bi = lane;
                #pragma unroll
                for (int off = 16; off; off >>= 1) {
                    float ov = __shfl_xor_sync(0xffffffffu, bv, off);
                    int   oi = __shfl_xor_sync(0xffffffffu, bi, off);
                    if (ov > bv || (ov == bv && oi < bi)) { bv = ov; bi = oi; }
                }
                if (lane == 0) localAcc += (bi == lbl) ? 1 : 0;
            }
        }
    }
    if (lane == 0) {
        int pi = b * 32 + gw;
        g_lossP[pi] += localLoss;
        if (layer == LL - 1) g_accP[pi] = localAcc;
    }
}

__global__ void k_final(float* __restrict__ out) {
    __shared__ float red[8];
    int t = threadIdx.x;  // 256
    float ls = 0.f, ac = 0.f;
    for (int i = t; i < BB * 32; i += 256) { ls += g_lossP[i]; ac += (float)g_accP[i]; }
    float L = blockSum(ls, red);
    float A = blockSum(ac, red);
    if (t == 0) {
        out[0] = L / (float)(BB * QN * LL);
        out[1] = A / (float)(BB * QN);
    }
}

// ---------------- launch ----------------
extern "C" void kernel_launch(void* const* d_in, const int* in_sizes, int n_in,
                              void* d_out, int out_size)
{
    const float* V_feat = (const float*)d_in[0];
    const float* P_feat = (const float*)d_in[1];
    const int*   qy     = (const int*)  d_in[2];
    const float* igbW   = (const float*)d_in[3];
    const float* igbB   = (const float*)d_in[4];
    const float* igbS   = (const float*)d_in[5];
    const float* pgbW   = (const float*)d_in[6];
    const float* pgbB   = (const float*)d_in[7];
    const float* pgbS   = (const float*)d_in[8];
    const float* alpha  = (const float*)d_in[9];
    const float* beta   = (const float*)d_in[10];
    float* out = (float*)d_out;

    float *pV, *pV0, *pGemm, *pP, *pP0, *pPgemm, *pPa, *pSim, *pSimQ, *pG, *pW;
    __nv_bfloat16 *pVh, *pVl, *pMh, *pMl, *pPMh, *pPMl, *pPah, *pPal, *piWh, *piWl, *ppWh, *ppWl;
    int *pIdx;
    cudaGetSymbolAddress((void**)&pV,    g_V);
    cudaGetSymbolAddress((void**)&pV0,   g_V0);
    cudaGetSymbolAddress((void**)&pVh,   g_Vh);
    cudaGetSymbolAddress((void**)&pVl,   g_Vl);
    cudaGetSymbolAddress((void**)&pMh,   g_Mh);
    cudaGetSymbolAddress((void**)&pMl,   g_Ml);
    cudaGetSymbolAddress((void**)&pGemm, g_gemm);
    cudaGetSymbolAddress((void**)&pP,    g_P);
    cudaGetSymbolAddress((void**)&pP0,   g_P0);
    cudaGetSymbolAddress((void**)&pPMh,  g_PMh);
    cudaGetSymbolAddress((void**)&pPMl,  g_PMl);
    cudaGetSymbolAddress((void**)&pPgemm,g_Pgemm);
    cudaGetSymbolAddress((void**)&pPa,   g_Pa);
    cudaGetSymbolAddress((void**)&pPah,  g_Pah);
    cudaGetSymbolAddress((void**)&pPal,  g_Pal);
    cudaGetSymbolAddress((void**)&pSim,  g_sim);
    cudaGetSymbolAddress((void**)&pSimQ, g_simQ);
    cudaGetSymbolAddress((void**)&pG,    g_G);
    cudaGetSymbolAddress((void**)&piWh,  g_iWh);
    cudaGetSymbolAddress((void**)&piWl,  g_iWl);
    cudaGetSymbolAddress((void**)&ppWh,  g_pWh);
    cudaGetSymbolAddress((void**)&ppWl,  g_pWl);
    cudaGetSymbolAddress((void**)&pW,    g_w);
    cudaGetSymbolAddress((void**)&pIdx,  g_idx);

    const int WN = LL * DD * DD;
    k_zero<<<(BB * 32 + 255) / 256, 256>>>();
    k_splitW<<<(WN + 255) / 256, 256>>>(igbW, piWh, piWl, WN);
    k_splitW<<<(WN + 255) / 256, 256>>>(pgbW, ppWh, ppWl, WN);
    k_padV<<<BB * (NPAD - NTOT), 128>>>(pVh, pVl);
    k_init<<<BB * NTOT, 128>>>(V_feat, pV, pV0, pVh, pVl, NTOT, NPAD);
    k_init<<<BB * NWAY, 128>>>(P_feat, pP, pP0, nullptr, nullptr, NWAY, NWAY);

    for (int i = 0; i < LL; i++) {
        // ---- instance branch ----
        k_gemm_bf<<<dim3(3, 3, BB), 128>>>(pVh, pVl, pVh, pVl, pSim,
            NTOT, NTOT, NTOT, (size_t)NPAD * DD, (size_t)NPAD * DD, (size_t)NTOT * NTOT);
        k_topk<<<(BB * NTOT + 3) / 4, 128>>>(pSim, NTOT, BB * NTOT, pIdx, pW);
        k_gather<<<BB * NTOT, 128>>>(pV, pIdx, pW, pMh, pMl, NTOT);
        k_gemm_bf<<<dim3(8, (BB * NTOT) / 64, 1), 128>>>(pMh, pMl,
            piWh + (size_t)i * DD * DD, piWl + (size_t)i * DD * DD, pGemm,
            BB * NTOT, DD, DD, 0, 0, 0);
        k_epi<<<BB * NTOT, 128>>>(pV, pV0, pGemm, igbB + (size_t)i * DD, igbS, i,
                                  pVh, pVl, NTOT, NPAD);
        // ---- prototype branch ----
        k_proto<<<BB, 256>>>(pP, pPMh, pPMl);
        k_gemm_bf<<<dim3(8, (BB * NWAY) / 64, 1), 128>>>(pPMh, pPMl,
            ppWh + (size_t)i * DD * DD, ppWl + (size_t)i * DD * DD, pPgemm,
            BB * NWAY, DD, DD, 0, 0, 0);
        k_epi<<<BB * NWAY, 128>>>(pP, pP0, pPgemm, pgbB + (size_t)i * DD, pgbS, i,
                                  nullptr, nullptr, NWAY, NWAY);
        // ---- centers, adapted prototypes, guidance ----
        k_vc_pa<<<dim3(BB, NWPAD), 128>>>(pV, pP, pPa, pPah, pPal, alpha);
        k_gram<<<BB, 256>>>(pPa, pG);
        k_gemm_bf<<<dim3(1, 3, BB), 128>>>(pVh, pVl, pPah, pPal, pSimQ,
            NPAD, NWPAD, NWPAD, (size_t)NPAD * DD, (size_t)NWPAD * DD, (size_t)NPAD * NWPAD);
        k_guide2<<<dim3(BB, 4), 256>>>(pV, pVh, pVl, pPa, pG, pSimQ, beta, qy, i);
    }
    k_final<<<1, 256>>>(out);
}

// round 6
// speedup vs baseline: 2.4934x; 1.0064x over previous
#include <cuda_runtime.h>
#include <cuda_bf16.h>
#include <math.h>
#include <stdint.h>

// ---------------- problem constants ----------------
#define BB    256
#define NTOT  175
#define NPAD  192     // padded rows for V bf16 arrays (multiple of 64)
#define NWAY  20
#define NWPAD 64      // padded Pa rows
#define KSHOT 5
#define QN    75
#define DD    512
#define LL    4
#define KNEI  5
#define TAUINV 10.0f
#define NKQ   (NWAY*KSHOT)

// ---------------- device scratch ----------------
__device__ float g_V   [(size_t)BB*NTOT*DD];
__device__ float g_V0  [(size_t)BB*NTOT*DD];
__device__ __nv_bfloat16 g_Vh[(size_t)BB*NPAD*DD];
__device__ __nv_bfloat16 g_Vl[(size_t)BB*NPAD*DD];
__device__ __nv_bfloat16 g_Mh[(size_t)BB*NTOT*DD];
__device__ __nv_bfloat16 g_Ml[(size_t)BB*NTOT*DD];
__device__ float g_gemm[(size_t)BB*NTOT*DD];
__device__ float g_P    [(size_t)BB*NWAY*DD];
__device__ float g_P0   [(size_t)BB*NWAY*DD];
__device__ __nv_bfloat16 g_PMh[(size_t)BB*NWAY*DD];
__device__ __nv_bfloat16 g_PMl[(size_t)BB*NWAY*DD];
__device__ float g_Pgemm[(size_t)BB*NWAY*DD];
__device__ float g_Pa   [(size_t)BB*NWAY*DD];
__device__ __nv_bfloat16 g_Pah[(size_t)BB*NWPAD*DD];
__device__ __nv_bfloat16 g_Pal[(size_t)BB*NWPAD*DD];
__device__ float g_sim [(size_t)BB*NTOT*NTOT];
__device__ float g_simQ[(size_t)BB*NPAD*NWPAD];
__device__ float g_G   [(size_t)BB*NWAY*NWAY];
__device__ __nv_bfloat16 g_iWh[(size_t)LL*DD*DD];
__device__ __nv_bfloat16 g_iWl[(size_t)LL*DD*DD];
__device__ __nv_bfloat16 g_pWh[(size_t)LL*DD*DD];
__device__ __nv_bfloat16 g_pWl[(size_t)LL*DD*DD];
__device__ float g_lossP[BB*32];
__device__ int   g_accP [BB*32];

// ---------------- helpers ----------------
__device__ __forceinline__ float blockSum(float v, float* red) {
    int tid = threadIdx.x;
    #pragma unroll
    for (int off = 16; off; off >>= 1) v += __shfl_down_sync(0xffffffffu, v, off);
    if ((tid & 31) == 0) red[tid >> 5] = v;
    __syncthreads();
    float r = 0.f;
    int nw = blockDim.x >> 5;
    if (tid < 32) {
        if (tid < nw) r = red[tid];
        #pragma unroll
        for (int off = 16; off; off >>= 1) r += __shfl_down_sync(0xffffffffu, r, off);
        if (tid == 0) red[0] = r;
    }
    __syncthreads();
    r = red[0];
    __syncthreads();
    return r;
}

__device__ __forceinline__ float warpSum(float v) {
    #pragma unroll
    for (int off = 16; off; off >>= 1) v += __shfl_xor_sync(0xffffffffu, v, off);
    return v;
}

__device__ __forceinline__ uint32_t smem_u32(const void* p) {
    return (uint32_t)__cvta_generic_to_shared(p);
}

__device__ __forceinline__ void cpasync16(uint32_t dst, const void* src) {
    asm volatile("cp.async.ca.shared.global [%0], [%1], 16;" :: "r"(dst), "l"(src));
}
__device__ __forceinline__ void cpcommit() { asm volatile("cp.async.commit_group;"); }
__device__ __forceinline__ void cpwait0()  { asm volatile("cp.async.wait_group 0;"); }

__device__ __forceinline__ void ldsm4(uint32_t& r0, uint32_t& r1, uint32_t& r2, uint32_t& r3,
                                      uint32_t addr) {
    asm volatile("ldmatrix.sync.aligned.m8n8.x4.shared.b16 {%0,%1,%2,%3}, [%4];"
                 : "=r"(r0), "=r"(r1), "=r"(r2), "=r"(r3) : "r"(addr));
}

__device__ __forceinline__ void mma16(float* c, const uint32_t* a, const uint32_t* b) {
    asm volatile(
        "mma.sync.aligned.m16n8k16.row.col.f32.bf16.bf16.f32 "
        "{%0,%1,%2,%3}, {%4,%5,%6,%7}, {%8,%9}, {%0,%1,%2,%3};"
        : "+f"(c[0]), "+f"(c[1]), "+f"(c[2]), "+f"(c[3])
        : "r"(a[0]), "r"(a[1]), "r"(a[2]), "r"(a[3]), "r"(b[0]), "r"(b[1]));
}

__device__ __forceinline__ void split1(float x, __nv_bfloat16& h, __nv_bfloat16& l) {
    h = __float2bfloat16(x);
    l = __float2bfloat16(x - __bfloat162float(h));
}
__device__ __forceinline__ void split4(float4 v, uint2& hv, uint2& lv) {
    __nv_bfloat16 h0,h1,h2,h3,l0,l1,l2,l3;
    split1(v.x,h0,l0); split1(v.y,h1,l1); split1(v.z,h2,l2); split1(v.w,h3,l3);
    hv.x = (uint32_t)__bfloat16_as_ushort(h0) | ((uint32_t)__bfloat16_as_ushort(h1) << 16);
    hv.y = (uint32_t)__bfloat16_as_ushort(h2) | ((uint32_t)__bfloat16_as_ushort(h3) << 16);
    lv.x = (uint32_t)__bfloat16_as_ushort(l0) | ((uint32_t)__bfloat16_as_ushort(l1) << 16);
    lv.y = (uint32_t)__bfloat16_as_ushort(l2) | ((uint32_t)__bfloat16_as_ushort(l3) << 16);
}

// ---------------- small kernels ----------------

__global__ void k_zero() {
    int i = blockIdx.x * 256 + threadIdx.x;
    if (i < BB * 32) { g_lossP[i] = 0.f; g_accP[i] = 0; }
}

__global__ void k_splitW(const float* __restrict__ src, __nv_bfloat16* __restrict__ h,
                         __nv_bfloat16* __restrict__ l, int n) {
    int i = blockIdx.x * 256 + threadIdx.x;
    if (i < n) { __nv_bfloat16 hh, ll; split1(src[i], hh, ll); h[i] = hh; l[i] = ll; }
}

__global__ void k_padV(__nv_bfloat16* __restrict__ Vh, __nv_bfloat16* __restrict__ Vl) {
    int b = blockIdx.x / (NPAD - NTOT);
    int r = NTOT + blockIdx.x % (NPAD - NTOT);
    size_t off = ((size_t)b * NPAD + r) * DD;
    int t = threadIdx.x;  // 128
    ((uint2*)(Vh + off))[t] = make_uint2(0, 0);
    ((uint2*)(Vl + off))[t] = make_uint2(0, 0);
}

// l2-normalize; optionally also emit bf16 hi/lo into padded array
__global__ void k_init(const float* __restrict__ in, float* __restrict__ out,
                       float* __restrict__ out0, __nv_bfloat16* __restrict__ oh,
                       __nv_bfloat16* __restrict__ ol, int rowsPerB, int padStride) {
    __shared__ float red[8];
    int row = blockIdx.x;
    int t = threadIdx.x;  // 128
    float4 v = ((const float4*)(in + (size_t)row * DD))[t];
    float ss = v.x*v.x + v.y*v.y + v.z*v.z + v.w*v.w;
    ss = blockSum(ss, red);
    float inv = 1.f / fmaxf(sqrtf(ss), 1e-12f);
    float4 o = make_float4(v.x*inv, v.y*inv, v.z*inv, v.w*inv);
    ((float4*)(out  + (size_t)row * DD))[t] = o;
    ((float4*)(out0 + (size_t)row * DD))[t] = o;
    if (oh) {
        int b = row / rowsPerB, n = row % rowsPerB;
        size_t po = ((size_t)b * padStride + n) * DD;
        uint2 hv, lv; split4(o, hv, lv);
        ((uint2*)(oh + po))[t] = hv;
        ((uint2*)(ol + po))[t] = lv;
    }
}

// ============== bf16 hi/lo split tensor-core NT GEMM (cp.async pipeline) ==============
// C[m,n] = sum_k A[m,k]*B[n,k]; fp32-equivalent via Ah*Bh + Ah*Bl + Al*Bh. K = 512.
// 80B-padded smem rows -> conflict-free ldmatrix; double-buffered cp.async.
template<int BM, int BN, int WARPS_M, int WARPS_N>
__global__ __launch_bounds__(WARPS_M*WARPS_N*32) void k_gemm_bf(
    const __nv_bfloat16* __restrict__ Ah, const __nv_bfloat16* __restrict__ Al,
    const __nv_bfloat16* __restrict__ Bh, const __nv_bfloat16* __restrict__ Bl,
    float* __restrict__ C, int M, int N, int ldc,
    size_t strA, size_t strB, size_t strC)
{
    constexpr int NT = WARPS_M * WARPS_N * 32;
    constexpr int WM = BM / WARPS_M, WN = BN / WARPS_N;
    constexpr int TM = WM / 16, TN = WN / 8;
    constexpr int SA = BM * 80, SB = BN * 80;
    constexpr int OFF_AL = SA, OFF_BH = 2*SA, OFF_BL = 2*SA + SB;
    constexpr int GSTG_ = 2*SA + 2*SB;
    constexpr int PT_A = (BM * 4) / NT;   // 16B chunks per thread per array
    constexpr int PT_B = (BN * 4) / NT;

    extern __shared__ __align__(16) uint8_t dynsmem[];

    int tid = threadIdx.x;
    int m0 = blockIdx.y * BM, n0 = blockIdx.x * BN;
    const __nv_bfloat16* pAh = Ah + (size_t)blockIdx.z * strA + (size_t)m0 * DD;
    const __nv_bfloat16* pAl = Al + (size_t)blockIdx.z * strA + (size_t)m0 * DD;
    const __nv_bfloat16* pBh = Bh + (size_t)blockIdx.z * strB + (size_t)n0 * DD;
    const __nv_bfloat16* pBl = Bl + (size_t)blockIdx.z * strB + (size_t)n0 * DD;
    float* Cb = C + (size_t)blockIdx.z * strC;

    int warp = tid >> 5, lane = tid & 31;
    int warpM = warp / WARPS_N, warpN = warp % WARPS_N;
    int j = lane >> 3, r8 = lane & 7;

    uint32_t offA[TM], offB[TN/2];
    #pragma unroll
    for (int mt = 0; mt < TM; mt++) {
        int row = warpM * WM + mt * 16 + (j & 1) * 8 + r8;
        offA[mt] = (uint32_t)(row * 80 + (j >> 1) * 16);
    }
    #pragma unroll
    for (int nt2 = 0; nt2 < TN/2; nt2++) {
        int n = warpN * WN + nt2 * 16 + (j >> 1) * 8 + r8;
        offB[nt2] = (uint32_t)(n * 80 + (j & 1) * 16);
    }
    uint32_t sbase = smem_u32(dynsmem);

    float acc[TM][TN][4];
    #pragma unroll
    for (int mt = 0; mt < TM; mt++)
        #pragma unroll
        for (int nt = 0; nt < TN; nt++)
            #pragma unroll
            for (int r = 0; r < 4; r++) acc[mt][nt][r] = 0.f;

    auto issue = [&](int st, int kg) {
        uint32_t sb = sbase + st * GSTG_;
        #pragma unroll
        for (int i = 0; i < PT_A; i++) {
            int c = tid + i * NT; int r = c >> 2, kc = c & 3;
            cpasync16(sb +          r*80 + kc*16, pAh + (size_t)r*DD + kg + kc*8);
            cpasync16(sb + OFF_AL + r*80 + kc*16, pAl + (size_t)r*DD + kg + kc*8);
        }
        #pragma unroll
        for (int i = 0; i < PT_B; i++) {
            int c = tid + i * NT; int r = c >> 2, kc = c & 3;
            cpasync16(sb + OFF_BH + r*80 + kc*16, pBh + (size_t)r*DD + kg + kc*8);
            cpasync16(sb + OFF_BL + r*80 + kc*16, pBl + (size_t)r*DD + kg + kc*8);
        }
        cpcommit();
    };

    issue(0, 0);
    int buf = 0;
    const int iters = DD / 32;   // 16
    for (int it = 0; it < iters; it++) {
        cpwait0();
        __syncthreads();
        if (it + 1 < iters) issue(buf ^ 1, (it + 1) * 32);
        uint32_t sb = sbase + buf * GSTG_;
        #pragma unroll
        for (int s = 0; s < 2; s++) {
            uint32_t so = s * 32;
            uint32_t ah[TM][4], al[TM][4], bh[TN][2], bl[TN][2];
            #pragma unroll
            for (int mt = 0; mt < TM; mt++) {
                ldsm4(ah[mt][0], ah[mt][1], ah[mt][2], ah[mt][3], sb + offA[mt] + so);
                ldsm4(al[mt][0], al[mt][1], al[mt][2], al[mt][3], sb + OFF_AL + offA[mt] + so);
            }
            #pragma unroll
            for (int nt2 = 0; nt2 < TN/2; nt2++) {
                uint32_t q0,q1,q2,q3;
                ldsm4(q0,q1,q2,q3, sb + OFF_BH + offB[nt2] + so);
                bh[nt2*2][0]=q0; bh[nt2*2][1]=q1; bh[nt2*2+1][0]=q2; bh[nt2*2+1][1]=q3;
                ldsm4(q0,q1,q2,q3, sb + OFF_BL + offB[nt2] + so);
                bl[nt2*2][0]=q0; bl[nt2*2][1]=q1; bl[nt2*2+1][0]=q2; bl[nt2*2+1][1]=q3;
            }
            #pragma unroll
            for (int mt = 0; mt < TM; mt++)
                #pragma unroll
                for (int nt = 0; nt < TN; nt++) {
                    mma16(acc[mt][nt], ah[mt], bh[nt]);
                    mma16(acc[mt][nt], ah[mt], bl[nt]);
                    mma16(acc[mt][nt], al[mt], bh[nt]);
                }
        }
        buf ^= 1;
    }

    #pragma unroll
    for (int mt = 0; mt < TM; mt++) {
        #pragma unroll
        for (int nt = 0; nt < TN; nt++) {
            int row = m0 + warpM * WM + mt * 16 + (lane >> 2);
            int col = n0 + warpN * WN + nt * 8 + (lane & 3) * 2;
            if (row < M) {
                if (col < N)     Cb[(size_t)row * ldc + col]     = acc[mt][nt][0];
                if (col + 1 < N) Cb[(size_t)row * ldc + col + 1] = acc[mt][nt][1];
            }
            if (row + 8 < M) {
                if (col < N)     Cb[(size_t)(row + 8) * ldc + col]     = acc[mt][nt][2];
                if (col + 1 < N) Cb[(size_t)(row + 8) * ldc + col + 1] = acc[mt][nt][3];
            }
        }
    }
}

// fused instance-branch sparse step: top-5 + softmax (warp 0) then gather (128 thr)
__global__ __launch_bounds__(128) void k_sparse(
    const float* __restrict__ sim, const float* __restrict__ V,
    __nv_bfloat16* __restrict__ mh, __nv_bfloat16* __restrict__ ml)
{
    __shared__ float sW[KNEI];
    __shared__ int   sI[KNEI];
    int row = blockIdx.x;
    int b = row / NTOT;
    int tid = threadIdx.x, lane = tid & 31;
    if (tid < 32) {
        const float* sr = sim + (size_t)row * NTOT;
        float v[6];
        #pragma unroll
        for (int jj = 0; jj < 6; jj++) {
            int c = lane + jj * 32;
            v[jj] = (c < NTOT) ? sr[c] : -INFINITY;
        }
        float cv[KNEI]; int ci[KNEI];
        #pragma unroll
        for (int p = 0; p < KNEI; p++) {
            float bv = -INFINITY; int bc = 0x7fffffff;
            #pragma unroll
            for (int jj = 0; jj < 6; jj++)
                if (v[jj] > bv) { bv = v[jj]; bc = lane + jj * 32; }
            #pragma unroll
            for (int off = 16; off; off >>= 1) {
                float ov = __shfl_down_sync(0xffffffffu, bv, off);
                int   oc = __shfl_down_sync(0xffffffffu, bc, off);
                if (ov > bv || (ov == bv && oc < bc)) { bv = ov; bc = oc; }
            }
            bv = __shfl_sync(0xffffffffu, bv, 0);
            bc = __shfl_sync(0xffffffffu, bc, 0);
            cv[p] = bv; ci[p] = bc;
            if ((bc & 31) == lane) v[bc >> 5] = -INFINITY;
        }
        if (lane == 0) {
            float mx = cv[0], e[KNEI], s = 0.f;
            #pragma unroll
            for (int p = 0; p < KNEI; p++) { e[p] = expf((cv[p] - mx) * TAUINV); s += e[p]; }
            float inv = 1.f / s;
            #pragma unroll
            for (int p = 0; p < KNEI; p++) { sW[p] = e[p] * inv; sI[p] = ci[p]; }
        }
    }
    __syncthreads();
    float wj[KNEI]; int ji[KNEI];
    #pragma unroll
    for (int p = 0; p < KNEI; p++) { wj[p] = sW[p]; ji[p] = sI[p]; }
    const float* base = V + (size_t)b * NTOT * DD;
    float4 acc = make_float4(0,0,0,0);
    #pragma unroll
    for (int p = 0; p < KNEI; p++) {
        float4 x = ((const float4*)(base + (size_t)ji[p] * DD))[tid];
        acc.x += wj[p]*x.x; acc.y += wj[p]*x.y; acc.z += wj[p]*x.z; acc.w += wj[p]*x.w;
    }
    uint2 hv, lv; split4(acc, hv, lv);
    ((uint2*)(mh + (size_t)row * DD))[tid] = hv;
    ((uint2*)(ml + (size_t)row * DD))[tid] = lv;
}

// fused prototype branch: sims + top-5 softmax + gather -> PMsg hi/lo
__global__ __launch_bounds__(256) void k_proto(const float* __restrict__ P,
                                               __nv_bfloat16* __restrict__ mh,
                                               __nv_bfloat16* __restrict__ ml)
{
    __shared__ float sP[NWAY * DD];
    __shared__ float sSim[NWAY][NWAY];
    __shared__ float sW[NWAY][KNEI];
    __shared__ int   sI[NWAY][KNEI];
    int b = blockIdx.x, tid = threadIdx.x;
    const float* Pb = P + (size_t)b * NWAY * DD;
    for (int i = tid; i < NWAY * DD; i += 256) sP[i] = Pb[i];
    __syncthreads();
    int warp = tid >> 5, lane = tid & 31;
    for (int p = warp; p < NWAY * NWAY; p += 8) {
        int r = p / NWAY, c = p % NWAY;
        float d = 0.f;
        for (int i = lane; i < DD; i += 32) d += sP[r * DD + i] * sP[c * DD + i];
        d = warpSum(d);
        if (lane == 0) sSim[r][c] = d;
    }
    __syncthreads();
    if (tid < NWAY) {
        float v[NWAY];
        #pragma unroll
        for (int c = 0; c < NWAY; c++) v[c] = sSim[tid][c];
        float cv[KNEI]; int ci[KNEI];
        #pragma unroll
        for (int p = 0; p < KNEI; p++) {
            float bv = -INFINITY; int bc = 0;
            #pragma unroll
            for (int c = 0; c < NWAY; c++)
                if (v[c] > bv) { bv = v[c]; bc = c; }
            cv[p] = bv; ci[p] = bc; v[bc] = -INFINITY;
        }
        float mx = cv[0], e[KNEI], s = 0.f;
        #pragma unroll
        for (int p = 0; p < KNEI; p++) { e[p] = expf((cv[p] - mx) * TAUINV); s += e[p]; }
        float inv = 1.f / s;
        #pragma unroll
        for (int p = 0; p < KNEI; p++) { sW[tid][p] = e[p] * inv; sI[tid][p] = ci[p]; }
    }
    __syncthreads();
    size_t base = (size_t)b * NWAY * DD;
    for (int e = tid; e < NWAY * DD; e += 256) {
        int r = e >> 9, d = e & (DD - 1);
        float a = 0.f;
        #pragma unroll
        for (int p = 0; p < KNEI; p++) a += sW[r][p] * sP[sI[r][p] * DD + d];
        __nv_bfloat16 hh, llv; split1(a, hh, llv);
        mh[base + e] = hh; ml[base + e] = llv;
    }
}

// x = l2n(0.8*(x + s*tanh(G + bias)) + 0.2*x0); optionally emit bf16 hi/lo (padded)
__global__ void k_epi(float* __restrict__ X, const float* __restrict__ X0,
                      const float* __restrict__ G, const float* __restrict__ bias,
                      const float* __restrict__ scaleArr, int layer,
                      __nv_bfloat16* __restrict__ oh, __nv_bfloat16* __restrict__ ol,
                      int rowsPerB, int padStride)
{
    __shared__ float red[8];
    int row = blockIdx.x;
    float s = scaleArr[layer];
    int t = threadIdx.x;  // 128
    float4 vv = ((const float4*)(X  + (size_t)row * DD))[t];
    float4 gg = ((const float4*)(G  + (size_t)row * DD))[t];
    float4 bb = ((const float4*)(bias))[t];
    float4 v0 = ((const float4*)(X0 + (size_t)row * DD))[t];
    float4 r4;
    r4.x = 0.8f*(vv.x + s*tanhf(gg.x + bb.x)) + 0.2f*v0.x;
    r4.y = 0.8f*(vv.y + s*tanhf(gg.y + bb.y)) + 0.2f*v0.y;
    r4.z = 0.8f*(vv.z + s*tanhf(gg.z + bb.z)) + 0.2f*v0.z;
    r4.w = 0.8f*(vv.w + s*tanhf(gg.w + bb.w)) + 0.2f*v0.w;
    float ss = r4.x*r4.x + r4.y*r4.y + r4.z*r4.z + r4.w*r4.w;
    ss = blockSum(ss, red);
    float inv = 1.f / fmaxf(sqrtf(ss), 1e-12f);
    r4.x*=inv; r4.y*=inv; r4.z*=inv; r4.w*=inv;
    ((float4*)(X + (size_t)row * DD))[t] = r4;
    if (oh) {   // refresh bf16 hi/lo mirror (simsQ / next sim GEMM consume this)
        int b = row / rowsPerB, n = row % rowsPerB;
        size_t po = ((size_t)b * padStride + n) * DD;
        uint2 hv, lv; split4(r4, hv, lv);
        ((uint2*)(oh + po))[t] = hv;
        ((uint2*)(ol + po))[t] = lv;
    }
}

// VC + Pa (f32 + bf16 hi/lo with zero padding rows)
__global__ void k_vc_pa(const float* __restrict__ V, const float* __restrict__ P,
                        float* __restrict__ Pa, __nv_bfloat16* __restrict__ Pah,
                        __nv_bfloat16* __restrict__ Pal, const float* __restrict__ alphaPtr)
{
    __shared__ float red[8];
    int b = blockIdx.x, c = blockIdx.y;
    int t = threadIdx.x;  // 128
    if (c >= NWAY) {
        size_t po = ((size_t)b * NWPAD + c) * DD;
        ((uint2*)(Pah + po))[t] = make_uint2(0, 0);
        ((uint2*)(Pal + po))[t] = make_uint2(0, 0);
        return;
    }
    const float* base = V + ((size_t)b * NTOT + (size_t)c * KSHOT) * DD;
    float4 s4 = make_float4(0,0,0,0);
    #pragma unroll
    for (int k = 0; k < KSHOT; k++) {
        float4 x = ((const float4*)(base + (size_t)k * DD))[t];
        s4.x += x.x; s4.y += x.y; s4.z += x.z; s4.w += x.w;
    }
    s4.x *= 0.2f; s4.y *= 0.2f; s4.z *= 0.2f; s4.w *= 0.2f;
    float ss = s4.x*s4.x + s4.y*s4.y + s4.z*s4.z + s4.w*s4.w;
    ss = blockSum(ss, red);
    float inv = 1.f / fmaxf(sqrtf(ss), 1e-12f);
    float a = *alphaPtr;
    float4 p4 = ((const float4*)(P + ((size_t)b * NWAY + c) * DD))[t];
    float4 pa;
    pa.x = a*p4.x + (1.f-a)*s4.x*inv;
    pa.y = a*p4.y + (1.f-a)*s4.y*inv;
    pa.z = a*p4.z + (1.f-a)*s4.z*inv;
    pa.w = a*p4.w + (1.f-a)*s4.w*inv;
    float ss2 = pa.x*pa.x + pa.y*pa.y + pa.z*pa.z + pa.w*pa.w;
    ss2 = blockSum(ss2, red);
    float inv2 = 1.f / fmaxf(sqrtf(ss2), 1e-12f);
    pa.x*=inv2; pa.y*=inv2; pa.z*=inv2; pa.w*=inv2;
    ((float4*)(Pa + ((size_t)b * NWAY + c) * DD))[t] = pa;
    size_t po = ((size_t)b * NWPAD + c) * DD;
    uint2 hv, lv; split4(pa, hv, lv);
    ((uint2*)(Pah + po))[t] = hv;
    ((uint2*)(Pal + po))[t] = lv;
}

// Gram matrix G = Pa . Pa^T (20x20 per batch)
__global__ __launch_bounds__(256) void k_gram(const float* __restrict__ Pa,
                                              float* __restrict__ G)
{
    __shared__ float sP[NWAY * DD];
    int b = blockIdx.x, tid = threadIdx.x;
    const float* Pb = Pa + (size_t)b * NWAY * DD;
    for (int i = tid; i < NWAY * DD; i += 256) sP[i] = Pb[i];
    __syncthreads();
    int w = tid >> 5, lane = tid & 31;
    for (int p = w; p < NWAY * NWAY; p += 8) {
        int i = p / NWAY, jc = p % NWAY;
        float d = 0.f;
        for (int k = lane; k < DD; k += 32) d += sP[i * DD + k] * sP[jc * DD + k];
        d = warpSum(d);
        if (lane == 0) G[(size_t)b * NWAY * NWAY + p] = d;
    }
}

// warp-per-row guidance: softmax(sims), V' update, Gram-based logits/CE/acc.
// writeV=0 (last layer): only query rows, logits/CE/acc, no V writeback.
__global__ __launch_bounds__(256) void k_guide2(
    float* __restrict__ V, __nv_bfloat16* __restrict__ Vh, __nv_bfloat16* __restrict__ Vl,
    const float* __restrict__ Pa, const float* __restrict__ G,
    const float* __restrict__ simsQ, const float* __restrict__ betaPtr,
    const int* __restrict__ qy, int layer, int writeV)
{
    __shared__ float sPa[NWAY * DD];
    __shared__ float sG[NWAY * NWAY];
    __shared__ float sSoft[8][NWAY];
    int b = blockIdx.x;
    int tid = threadIdx.x, w = tid >> 5, lane = tid & 31;
    float beta = *betaPtr;
    if (writeV) {
        const float* PaB = Pa + (size_t)b * NWAY * DD;
        for (int i = tid; i < NWAY * DD; i += 256) sPa[i] = PaB[i];
    }
    for (int i = tid; i < NWAY * NWAY; i += 256) sG[i] = G[(size_t)b * NWAY * NWAY + i];
    __syncthreads();
    int gw = blockIdx.y * 8 + w;   // 0..31
    float localLoss = 0.f; int localAcc = 0;
    for (int r = gw; r < NTOT; r += 32) {
        if (!writeV && r < NKQ) continue;   // last layer: support rows contribute nothing
        float s = (lane < NWAY) ? simsQ[((size_t)b * NPAD + r) * NWPAD + lane] : -INFINITY;
        float mx = s;
        #pragma unroll
        for (int off = 16; off; off >>= 1) mx = fmaxf(mx, __shfl_xor_sync(0xffffffffu, mx, off));
        float e = (lane < NWAY) ? expf((s - mx) * TAUINV) : 0.f;
        float sum = warpSum(e);
        float soft = e / sum;
        // t_j = (G soft)_j via per-lane column dot (needs soft of all lanes)
        if (lane < NWAY) sSoft[w][lane] = soft;
        __syncwarp();
        float tj = 0.f;
        if (lane < NWAY) {
            #pragma unroll
            for (int m = 0; m < NWAY; m++) tj += sSoft[w][m] * sG[m * NWAY + lane];
        }
        float ob = 1.f - beta;
        float contrib = (lane < NWAY) ? soft * (2.f * beta * ob * s + ob * ob * tj) : 0.f;
        float n2 = beta * beta + warpSum(contrib);
        float invn = 1.f / fmaxf(sqrtf(n2), 1e-12f);
        if (writeV) {
            float* Vrow = V + ((size_t)b * NTOT + r) * DD;
            __nv_bfloat16* VhRow = Vh + ((size_t)b * NPAD + r) * DD;
            __nv_bfloat16* VlRow = Vl + ((size_t)b * NPAD + r) * DD;
            #pragma unroll
            for (int i = 0; i < 16; i++) {
                int d = lane + 32 * i;
                float g = 0.f;
                #pragma unroll
                for (int m = 0; m < NWAY; m++) g += sSoft[w][m] * sPa[m * DD + d];
                float nv = (beta * Vrow[d] + ob * g) * invn;
                Vrow[d] = nv;
                __nv_bfloat16 hh, ll; split1(nv, hh, ll);
                VhRow[d] = hh; VlRow[d] = ll;
            }
        }
        if (r >= NKQ) {
            float logit = (lane < NWAY) ? 5.f * invn * (beta * s + ob * tj) : -INFINITY;
            float m2 = logit;
            #pragma unroll
            for (int off = 16; off; off >>= 1) m2 = fmaxf(m2, __shfl_xor_sync(0xffffffffu, m2, off));
            float ee = (lane < NWAY) ? expf(logit - m2) : 0.f;
            float ssum = warpSum(ee);
            float lse = m2 + logf(ssum);
            int lbl = qy[b * QN + (r - NKQ)];
            float ll = __shfl_sync(0xffffffffu, logit, lbl);
            if (lane == 0) localLoss += lse - ll;
            if (layer == LL - 1) {
                float bv = logit; int bi = lane;
                #pragma unroll
                for (int off = 16; off; off >>= 1) {
                    float ov = __shfl_xor_sync(0xffffffffu, bv, off);
                    int   oi = __shfl_xor_sync(0xffffffffu, bi, off);
                    if (ov > bv || (ov == bv && oi < bi)) { bv = ov; bi = oi; }
                }
                if (lane == 0) localAcc += (bi == lbl) ? 1 : 0;
            }
        }
    }
    if (lane == 0) {
        int pi = b * 32 + gw;
        g_lossP[pi] += localLoss;
        if (layer == LL - 1) g_accP[pi] = localAcc;
    }
}

__global__ void k_final(float* __restrict__ out) {
    __shared__ float red[8];
    int t = threadIdx.x;  // 256
    float ls = 0.f, ac = 0.f;
    for (int i = t; i < BB * 32; i += 256) { ls += g_lossP[i]; ac += (float)g_accP[i]; }
    float L = blockSum(ls, red);
    float A = blockSum(ac, red);
    if (t == 0) {
        out[0] = L / (float)(BB * QN * LL);
        out[1] = A / (float)(BB * QN);
    }
}

// ---------------- launch ----------------
extern "C" void kernel_launch(void* const* d_in, const int* in_sizes, int n_in,
                              void* d_out, int out_size)
{
    const float* V_feat = (const float*)d_in[0];
    const float* P_feat = (const float*)d_in[1];
    const int*   qy     = (const int*)  d_in[2];
    const float* igbW   = (const float*)d_in[3];
    const float* igbB   = (const float*)d_in[4];
    const float* igbS   = (const float*)d_in[5];
    const float* pgbW   = (const float*)d_in[6];
    const float* pgbB   = (const float*)d_in[7];
    const float* pgbS   = (const float*)d_in[8];
    const float* alpha  = (const float*)d_in[9];
    const float* beta   = (const float*)d_in[10];
    float* out = (float*)d_out;

    float *pV, *pV0, *pGemm, *pP, *pP0, *pPgemm, *pPa, *pSim, *pSimQ, *pG;
    __nv_bfloat16 *pVh, *pVl, *pMh, *pMl, *pPMh, *pPMl, *pPah, *pPal, *piWh, *piWl, *ppWh, *ppWl;
    cudaGetSymbolAddress((void**)&pV,    g_V);
    cudaGetSymbolAddress((void**)&pV0,   g_V0);
    cudaGetSymbolAddress((void**)&pVh,   g_Vh);
    cudaGetSymbolAddress((void**)&pVl,   g_Vl);
    cudaGetSymbolAddress((void**)&pMh,   g_Mh);
    cudaGetSymbolAddress((void**)&pMl,   g_Ml);
    cudaGetSymbolAddress((void**)&pGemm, g_gemm);
    cudaGetSymbolAddress((void**)&pP,    g_P);
    cudaGetSymbolAddress((void**)&pP0,   g_P0);
    cudaGetSymbolAddress((void**)&pPMh,  g_PMh);
    cudaGetSymbolAddress((void**)&pPMl,  g_PMl);
    cudaGetSymbolAddress((void**)&pPgemm,g_Pgemm);
    cudaGetSymbolAddress((void**)&pPa,   g_Pa);
    cudaGetSymbolAddress((void**)&pPah,  g_Pah);
    cudaGetSymbolAddress((void**)&pPal,  g_Pal);
    cudaGetSymbolAddress((void**)&pSim,  g_sim);
    cudaGetSymbolAddress((void**)&pSimQ, g_simQ);
    cudaGetSymbolAddress((void**)&pG,    g_G);
    cudaGetSymbolAddress((void**)&piWh,  g_iWh);
    cudaGetSymbolAddress((void**)&piWl,  g_iWl);
    cudaGetSymbolAddress((void**)&ppWh,  g_pWh);
    cudaGetSymbolAddress((void**)&ppWl,  g_pWl);

    // allow 80KB dynamic smem for the big-tile GEMM (host attribute set; not an allocation)
    cudaFuncSetAttribute(k_gemm_bf<128,128,2,4>,
                         cudaFuncAttributeMaxDynamicSharedMemorySize, 81920);
    const int SM_BIG = 81920;     // 2 * (2*128*80 + 2*128*80)
    const int SM_SMALL = 40960;   // 2 * (2*64*80 + 2*64*80)

    const int WN = LL * DD * DD;
    k_zero<<<(BB * 32 + 255) / 256, 256>>>();
    k_splitW<<<(WN + 255) / 256, 256>>>(igbW, piWh, piWl, WN);
    k_splitW<<<(WN + 255) / 256, 256>>>(pgbW, ppWh, ppWl, WN);
    k_padV<<<BB * (NPAD - NTOT), 128>>>(pVh, pVl);
    k_init<<<BB * NTOT, 128>>>(V_feat, pV, pV0, pVh, pVl, NTOT, NPAD);
    k_init<<<BB * NWAY, 128>>>(P_feat, pP, pP0, nullptr, nullptr, NWAY, NWAY);

    for (int i = 0; i < LL; i++) {
        // ---- instance branch ----
        k_gemm_bf<64,64,2,2><<<dim3(3, 3, BB), 128, SM_SMALL>>>(pVh, pVl, pVh, pVl, pSim,
            NTOT, NTOT, NTOT, (size_t)NPAD * DD, (size_t)NPAD * DD, (size_t)NTOT * NTOT);
        k_sparse<<<BB * NTOT, 128>>>(pSim, pV, pMh, pMl);
        k_gemm_bf<128,128,2,4><<<dim3(4, (BB * NTOT) / 128, 1), 256, SM_BIG>>>(pMh, pMl,
            piWh + (size_t)i * DD * DD, piWl + (size_t)i * DD * DD, pGemm,
            BB * NTOT, DD, DD, 0, 0, 0);
        k_epi<<<BB * NTOT, 128>>>(pV, pV0, pGemm, igbB + (size_t)i * DD, igbS, i,
                                  pVh, pVl, NTOT, NPAD);
        // ---- prototype branch ----
        k_proto<<<BB, 256>>>(pP, pPMh, pPMl);
        k_gemm_bf<128,128,2,4><<<dim3(4, (BB * NWAY) / 128, 1), 256, SM_BIG>>>(pPMh, pPMl,
            ppWh + (size_t)i * DD * DD, ppWl + (size_t)i * DD * DD, pPgemm,
            BB * NWAY, DD, DD, 0, 0, 0);
        k_epi<<<BB * NWAY, 128>>>(pP, pP0, pPgemm, pgbB + (size_t)i * DD, pgbS, i,
                                  nullptr, nullptr, NWAY, NWAY);
        // ---- centers, adapted prototypes, guidance ----
        k_vc_pa<<<dim3(BB, NWPAD), 128>>>(pV, pP, pPa, pPah, pPal, alpha);
        k_gram<<<BB, 256>>>(pPa, pG);
        k_gemm_bf<64,64,2,2><<<dim3(1, 3, BB), 128, SM_SMALL>>>(pVh, pVl, pPah, pPal, pSimQ,
            NPAD, NWPAD, NWPAD, (size_t)NPAD * DD, (size_t)NWPAD * DD, (size_t)NPAD * NWPAD);
        int writeV = (i < LL - 1) ? 1 : 0;
        k_guide2<<<dim3(BB, 4), 256>>>(pV, pVh, pVl, pPa, pG, pSimQ, beta, qy, i, writeV);
    }
    k_final<<<1, 256>>>(out);
}